// round 6
// baseline (speedup 1.0000x reference)
#include <cuda_runtime.h>
#include <cstddef>

typedef unsigned long long ull;

// ---------------------------------------------------------------------------
// Problem constants
// ---------------------------------------------------------------------------
constexpr int B_   = 4;
constexpr int DIM  = 256;
constexpr int MID  = 128;
constexpr int HH   = 128;
constexpr int WW   = 128;

// ---------------------------------------------------------------------------
// Device scratch (no allocations allowed -> __device__ globals)
// ---------------------------------------------------------------------------
__device__ float g_p1[(size_t)B_ * MID * HH * WW];   // p1, then cp1, then s = cp1+cp2
__device__ float g_p2[(size_t)B_ * MID * HH * WW];   // p2
__device__ float g_t1[(size_t)B_ * DIM * HH * WW];   // bn1, then r (in-place)
__device__ float g_scale[1024];                      // p1:0 p2:128 c1:256 c2:512 p3:768
__device__ float g_bias[1024];

// ---------------------------------------------------------------------------
// Packed fp32x2 helpers (Blackwell FFMA2 path — only reachable via PTX)
// ---------------------------------------------------------------------------
__device__ __forceinline__ ull pk2(float lo, float hi) {
    ull r; asm("mov.b64 %0, {%1, %2};" : "=l"(r) : "f"(lo), "f"(hi)); return r;
}
__device__ __forceinline__ float2 unpk(ull v) {
    float2 f; asm("mov.b64 {%0, %1}, %2;" : "=f"(f.x), "=f"(f.y) : "l"(v)); return f;
}
__device__ __forceinline__ void fma2(ull& d, ull a, ull b) {
    asm("fma.rn.f32x2 %0, %1, %2, %0;" : "+l"(d) : "l"(a), "l"(b));
}

// ---------------------------------------------------------------------------
// BN folding: scale = g * rsqrt(v+eps); bias = b - m*scale
// ---------------------------------------------------------------------------
__global__ void bn_prep(const float* __restrict__ g, const float* __restrict__ b,
                        const float* __restrict__ m, const float* __restrict__ v,
                        float* __restrict__ scale, float* __restrict__ bias, int C)
{
    int i = blockIdx.x * blockDim.x + threadIdx.x;
    if (i < C) {
        float s = g[i] * rsqrtf(v[i] + 1e-5f);
        scale[i] = s;
        bias[i]  = b[i] - m[i] * s;
    }
}

// ---------------------------------------------------------------------------
// Fused conv + BN (+ optional add) (+ ReLU), packed-fp32x2 inner loop.
//
// Block tile: 128 cout x (4 rows x 32 cols) pixels, 256 threads,
// per-thread microtile 8 cout x 8 pixels held as 8 x 4 packed f32x2 accs.
//
// Weights staged DUPLICATED in smem as (w,w) 8B pairs -> inner-loop packed
// multiplier is a single broadcast LDS.64 (2 addrs/warp, conflict-free).
// Aligned pixel pairs come directly from LDS.64 (base is 16B aligned);
// odd-shift pairs are 4 register repacks per row.
// ---------------------------------------------------------------------------
template<int CIN, int KS, int CC, bool RELU, bool ADD>
__global__ __launch_bounds__(256, 2)
void conv_bn(const float* __restrict__ in, const float* __restrict__ wgt,
             const float* __restrict__ scale, const float* __restrict__ bias,
             const float* __restrict__ addsrc, float* __restrict__ out, int COUT)
{
    constexpr int TH2   = 4;
    constexpr int TW2   = 32;
    constexpr int BC    = 128;
    constexpr int PAD   = (KS - 1) / 2;
    constexpr int XROWS = TH2 + KS - 1;
    constexpr int SXW   = 36;               // padded row width (16B-aligned stride)
    constexpr int WN    = CC * KS * KS;     // weight entries per cout per chunk
    constexpr int W4    = WN / 4;

    __shared__ float sx[CC * XROWS * SXW];
    __shared__ ull   sw2[BC * WN];          // duplicated (w,w) pairs

    const int tid  = threadIdx.x;
    const int tc   = tid >> 4;              // 0..15 cout group (couts tc*8 .. tc*8+7)
    const int pg   = tid & 15;              // pixel group
    const int prow = pg >> 2;               // 0..3
    const int pcol = (pg & 3) * 8;          // 0,8,16,24

    const int bx = blockIdx.x;
    const int b  = bx >> 7;                 // 128 pixel-tiles per image
    const int t  = bx & 127;
    const int h0 = (t >> 2) * TH2;          // 32 row-tiles
    const int w0 = (t & 3) * TW2;           // 4 col-tiles
    const int co0 = blockIdx.y * BC;

    ull acc[8][4];
#pragma unroll
    for (int i = 0; i < 8; i++)
#pragma unroll
        for (int k = 0; k < 4; k++) acc[i][k] = 0ull;

    for (int ci0 = 0; ci0 < CIN; ci0 += CC) {
        __syncthreads();

        // ---- stage input patch: CC channels x XROWS x (TW2+KS-1), zero-padded ----
#pragma unroll 1
        for (int idx = tid; idx < CC * XROWS * SXW; idx += 256) {
            int cc  = idx % SXW;
            int t2  = idx / SXW;
            int rr  = t2 % XROWS;
            int ci  = t2 / XROWS;
            float val = 0.f;
            int gh = h0 - PAD + rr;
            int gw = w0 - PAD + cc;
            if (cc < TW2 + KS - 1 && (unsigned)gh < (unsigned)HH && (unsigned)gw < (unsigned)WW)
                val = in[(((size_t)b * CIN + ci0 + ci) * HH + gh) * WW + gw];
            sx[idx] = val;
        }

        // ---- stage weights duplicated: sw2[co][k] = (w,w) ----
        {
            const float4* wg4 = reinterpret_cast<const float4*>(wgt);
#pragma unroll 1
            for (int idx = tid; idx < BC * W4; idx += 256) {
                int co = idx / W4;
                int q  = idx % W4;
                float4 vv = wg4[(((size_t)(co0 + co) * CIN + ci0) * (KS * KS)) / 4 + q];
                ull* dst = &sw2[co * WN + q * 4];
                dst[0] = pk2(vv.x, vv.x);
                dst[1] = pk2(vv.y, vv.y);
                dst[2] = pk2(vv.z, vv.z);
                dst[3] = pk2(vv.w, vv.w);
            }
        }
        __syncthreads();

        // ---- compute ----
#pragma unroll 1
        for (int ci = 0; ci < CC; ci++) {
#pragma unroll
            for (int r = 0; r < KS; r++) {
                const ull* xr8 = reinterpret_cast<const ull*>(
                    &sx[(ci * XROWS + prow + r) * SXW + pcol]);
                if (KS == 3) {
                    ull pA[5], pO[4];
#pragma unroll
                    for (int k = 0; k < 5; k++) pA[k] = xr8[k];      // aligned LDS.64
#pragma unroll
                    for (int k = 0; k < 4; k++) {
                        float2 lo = unpk(pA[k]);
                        float2 hi = unpk(pA[k + 1]);
                        pO[k] = pk2(lo.y, hi.x);                      // odd-shift pairs
                    }
#pragma unroll
                    for (int i = 0; i < 8; i++) {
                        const ull* wp = &sw2[(tc * 8 + i) * WN + ci * 9 + r * 3];
                        ull wv0 = wp[0], wv1 = wp[1], wv2 = wp[2];
#pragma unroll
                        for (int k = 0; k < 4; k++) fma2(acc[i][k], pA[k],     wv0);
#pragma unroll
                        for (int k = 0; k < 4; k++) fma2(acc[i][k], pO[k],     wv1);
#pragma unroll
                        for (int k = 0; k < 4; k++) fma2(acc[i][k], pA[k + 1], wv2);
                    }
                } else {  // KS == 1
                    ull pA[4];
#pragma unroll
                    for (int k = 0; k < 4; k++) pA[k] = xr8[k];
#pragma unroll
                    for (int i = 0; i < 8; i++) {
                        ull wv = sw2[(tc * 8 + i) * WN + ci];
#pragma unroll
                        for (int k = 0; k < 4; k++) fma2(acc[i][k], pA[k], wv);
                    }
                }
            }
        }
    }

    // ---- epilogue: BN (+add) (+relu), vectorized float4 stores ----
    const int hh = h0 + prow;
#pragma unroll
    for (int i = 0; i < 8; i++) {
        const int co = co0 + tc * 8 + i;
        const float sc = scale[co];
        const float bi = bias[co];
        const size_t base = (((size_t)b * COUT + co) * HH + hh) * WW + w0 + pcol;
        float vv[8];
#pragma unroll
        for (int k = 0; k < 4; k++) {
            float2 u = unpk(acc[i][k]);
            vv[2 * k]     = u.x;
            vv[2 * k + 1] = u.y;
        }
#pragma unroll
        for (int j2 = 0; j2 < 2; j2++) {
            float4 o;
            o.x = vv[j2 * 4 + 0] * sc + bi;
            o.y = vv[j2 * 4 + 1] * sc + bi;
            o.z = vv[j2 * 4 + 2] * sc + bi;
            o.w = vv[j2 * 4 + 3] * sc + bi;
            if (ADD) {
                float4 ad = reinterpret_cast<const float4*>(addsrc + base)[j2];
                o.x += ad.x; o.y += ad.y; o.z += ad.z; o.w += ad.w;
            }
            if (RELU) {
                o.x = fmaxf(o.x, 0.f); o.y = fmaxf(o.y, 0.f);
                o.z = fmaxf(o.z, 0.f); o.w = fmaxf(o.w, 0.f);
            }
            reinterpret_cast<float4*>(out + base)[j2] = o;
        }
    }
}

// ---------------------------------------------------------------------------
// Corner pooling part 1: in-place reverse cummax over H on g_p1.
// One thread per (b, c, w) column; coalesced across w.
// ---------------------------------------------------------------------------
__global__ void colscan_kernel(float* __restrict__ p)
{
    int idx = blockIdx.x * blockDim.x + threadIdx.x;   // (b*MID + c)*WW + w
    if (idx >= B_ * MID * WW) return;
    int w  = idx % WW;
    int bc = idx / WW;
    float* col = p + (size_t)bc * HH * WW + w;
    float m = col[(HH - 1) * WW];
#pragma unroll 4
    for (int h = HH - 2; h >= 0; h--) {
        float v = col[h * WW];
        m = fmaxf(m, v);
        col[h * WW] = m;
    }
}

// ---------------------------------------------------------------------------
// Corner pooling part 2: reverse cummax over W of p2 (per row), added into s.
// One 128-thread block per (b, c, h) row; Hillis-Steele suffix-max in smem.
// ---------------------------------------------------------------------------
__global__ void rowscan_add_kernel(const float* __restrict__ p2, float* __restrict__ s)
{
    __shared__ float sm[WW];
    const int t = threadIdx.x;
    const size_t base = (size_t)blockIdx.x * WW;
    sm[t] = p2[base + t];
    __syncthreads();
#pragma unroll
    for (int off = 1; off < WW; off <<= 1) {
        float nv = sm[t];
        if (t + off < WW) nv = fmaxf(nv, sm[t + off]);
        __syncthreads();
        sm[t] = nv;
        __syncthreads();
    }
    s[base + t] += sm[t];
}

// ---------------------------------------------------------------------------
// Launch: p1, p2 -> corner pool -> bn1 -> bn2(+add,relu) -> p3
// ---------------------------------------------------------------------------
extern "C" void kernel_launch(void* const* d_in, const int* in_sizes, int n_in,
                              void* d_out, int out_size)
{
    (void)in_sizes; (void)n_in; (void)out_size;

    const float* x    = (const float*)d_in[0];
    const float* w_p1 = (const float*)d_in[1];
    const float* w_p2 = (const float*)d_in[6];
    const float* w_c1 = (const float*)d_in[11];
    const float* w_c2 = (const float*)d_in[16];
    const float* w_p3 = (const float*)d_in[21];

    float *p1, *p2, *t1, *sc, *bi;
    cudaGetSymbolAddress((void**)&p1, g_p1);
    cudaGetSymbolAddress((void**)&p2, g_p2);
    cudaGetSymbolAddress((void**)&t1, g_t1);
    cudaGetSymbolAddress((void**)&sc, g_scale);
    cudaGetSymbolAddress((void**)&bi, g_bias);

    // Fold all 5 batchnorms (offsets: p1=0, p2=128, c1=256, c2=512, p3=768)
    bn_prep<<<1, 256>>>((const float*)d_in[2],  (const float*)d_in[3],
                        (const float*)d_in[4],  (const float*)d_in[5],  sc + 0,   bi + 0,   MID);
    bn_prep<<<1, 256>>>((const float*)d_in[7],  (const float*)d_in[8],
                        (const float*)d_in[9],  (const float*)d_in[10], sc + 128, bi + 128, MID);
    bn_prep<<<1, 256>>>((const float*)d_in[12], (const float*)d_in[13],
                        (const float*)d_in[14], (const float*)d_in[15], sc + 256, bi + 256, DIM);
    bn_prep<<<1, 256>>>((const float*)d_in[17], (const float*)d_in[18],
                        (const float*)d_in[19], (const float*)d_in[20], sc + 512, bi + 512, DIM);
    bn_prep<<<1, 256>>>((const float*)d_in[22], (const float*)d_in[23],
                        (const float*)d_in[24], (const float*)d_in[25], sc + 768, bi + 768, DIM);

    const int PIX_TILES = B_ * (HH / 4) * (WW / 32);   // 512

    // p1 = relu(bn(conv3x3(x, w_p1)))   [256 -> 128]
    conv_bn<DIM, 3, 4, true, false><<<dim3(PIX_TILES, MID / 128), 256>>>(
        x, w_p1, sc + 0, bi + 0, nullptr, p1, MID);
    // p2 = relu(bn(conv3x3(x, w_p2)))   [256 -> 128]
    conv_bn<DIM, 3, 4, true, false><<<dim3(PIX_TILES, MID / 128), 256>>>(
        x, w_p2, sc + 128, bi + 128, nullptr, p2, MID);

    // corner pooling: p1 <- revcummax_H(p1); p1 += revcummax_W(p2)
    colscan_kernel<<<(B_ * MID * WW + 255) / 256, 256>>>(p1);
    rowscan_add_kernel<<<B_ * MID * HH, WW>>>(p2, p1);

    // t1 = bn(conv3x3(s, w_c1))  (no relu)   [128 -> 256]
    conv_bn<MID, 3, 4, false, false><<<dim3(PIX_TILES, DIM / 128), 256>>>(
        p1, w_c1, sc + 256, bi + 256, nullptr, t1, DIM);

    // t1 = relu(bn(conv1x1(x, w_c2)) + t1)   [256 -> 256], in-place add
    conv_bn<DIM, 1, 16, true, true><<<dim3(PIX_TILES, DIM / 128), 256>>>(
        x, w_c2, sc + 512, bi + 512, t1, t1, DIM);

    // out = relu(bn(conv3x3(r, w_p3)))       [256 -> 256]
    conv_bn<DIM, 3, 4, true, false><<<dim3(PIX_TILES, DIM / 128), 256>>>(
        t1, w_p3, sc + 768, bi + 768, nullptr, (float*)d_out, DIM);
}

// round 8
// speedup vs baseline: 1.0044x; 1.0044x over previous
#include <cuda_runtime.h>
#include <cstddef>

typedef unsigned long long ull;

// ---------------------------------------------------------------------------
// Problem constants
// ---------------------------------------------------------------------------
constexpr int B_   = 4;
constexpr int DIM  = 256;
constexpr int MID  = 128;
constexpr int HH   = 128;
constexpr int WW   = 128;

// ---------------------------------------------------------------------------
// Device scratch (no allocations allowed -> __device__ globals)
// ---------------------------------------------------------------------------
__device__ float g_p1[(size_t)B_ * MID * HH * WW];   // p1, then cp1, then s = cp1+cp2
__device__ float g_p2[(size_t)B_ * MID * HH * WW];   // p2
__device__ float g_t1[(size_t)B_ * DIM * HH * WW];   // bn1, then r (in-place)
__device__ float g_scale[1024];                      // p1:0 p2:128 c1:256 c2:512 p3:768
__device__ float g_bias[1024];

// ---------------------------------------------------------------------------
// Packed fp32x2 helpers (Blackwell FFMA2 path — only reachable via PTX)
// ---------------------------------------------------------------------------
__device__ __forceinline__ ull pk2(float lo, float hi) {
    ull r; asm("mov.b64 %0, {%1, %2};" : "=l"(r) : "f"(lo), "f"(hi)); return r;
}
__device__ __forceinline__ float2 unpk(ull v) {
    float2 f; asm("mov.b64 {%0, %1}, %2;" : "=f"(f.x), "=f"(f.y) : "l"(v)); return f;
}
__device__ __forceinline__ void fma2(ull& d, ull a, ull b) {
    asm("fma.rn.f32x2 %0, %1, %2, %0;" : "+l"(d) : "l"(a), "l"(b));
}

// ---------------------------------------------------------------------------
// BN folding: scale = g * rsqrt(v+eps); bias = b - m*scale
// ---------------------------------------------------------------------------
__global__ void bn_prep(const float* __restrict__ g, const float* __restrict__ b,
                        const float* __restrict__ m, const float* __restrict__ v,
                        float* __restrict__ scale, float* __restrict__ bias, int C)
{
    int i = blockIdx.x * blockDim.x + threadIdx.x;
    if (i < C) {
        float s = g[i] * rsqrtf(v[i] + 1e-5f);
        scale[i] = s;
        bias[i]  = b[i] - m[i] * s;
    }
}

// ---------------------------------------------------------------------------
// Fused conv + BN (+ optional add) (+ ReLU), packed-fp32x2 inner loop.
//
// Block tile: 128 cout x (4 rows x 32 cols) pixels, 256 threads,
// per-thread microtile 8 cout x 8 pixels held as 8 x 4 packed f32x2 accs.
//
// Weights staged DUPLICATED in smem as (w,w) 8B pairs -> inner-loop packed
// multiplier is a single broadcast LDS.64 (2 addrs/warp, conflict-free).
// Aligned pixel pairs come directly from LDS.64 (base is 16B aligned);
// odd-shift pairs are 4 register repacks per row.
// ---------------------------------------------------------------------------
template<int CIN, int KS, int CC, bool RELU, bool ADD>
__global__ __launch_bounds__(256, 2)
void conv_bn(const float* __restrict__ in, const float* __restrict__ wgt,
             const float* __restrict__ scale, const float* __restrict__ bias,
             const float* __restrict__ addsrc, float* __restrict__ out, int COUT)
{
    constexpr int TH2   = 4;
    constexpr int TW2   = 32;
    constexpr int BC    = 128;
    constexpr int PAD   = (KS - 1) / 2;
    constexpr int XROWS = TH2 + KS - 1;
    constexpr int SXW   = 36;               // padded row width (16B-aligned stride)
    constexpr int WN    = CC * KS * KS;     // weight entries per cout per chunk
    constexpr int W4    = WN / 4;

    __shared__ float sx[CC * XROWS * SXW];
    __shared__ ull   sw2[BC * WN];          // duplicated (w,w) pairs

    const int tid  = threadIdx.x;
    const int tc   = tid >> 4;              // 0..15 cout group (couts tc*8 .. tc*8+7)
    const int pg   = tid & 15;              // pixel group
    const int prow = pg >> 2;               // 0..3
    const int pcol = (pg & 3) * 8;          // 0,8,16,24

    const int bx = blockIdx.x;
    const int b  = bx >> 7;                 // 128 pixel-tiles per image
    const int t  = bx & 127;
    const int h0 = (t >> 2) * TH2;          // 32 row-tiles
    const int w0 = (t & 3) * TW2;           // 4 col-tiles
    const int co0 = blockIdx.y * BC;

    ull acc[8][4];
#pragma unroll
    for (int i = 0; i < 8; i++)
#pragma unroll
        for (int k = 0; k < 4; k++) acc[i][k] = 0ull;

    for (int ci0 = 0; ci0 < CIN; ci0 += CC) {
        __syncthreads();

        // ---- stage input patch: CC channels x XROWS x (TW2+KS-1), zero-padded ----
#pragma unroll 1
        for (int idx = tid; idx < CC * XROWS * SXW; idx += 256) {
            int cc  = idx % SXW;
            int t2  = idx / SXW;
            int rr  = t2 % XROWS;
            int ci  = t2 / XROWS;
            float val = 0.f;
            int gh = h0 - PAD + rr;
            int gw = w0 - PAD + cc;
            if (cc < TW2 + KS - 1 && (unsigned)gh < (unsigned)HH && (unsigned)gw < (unsigned)WW)
                val = in[(((size_t)b * CIN + ci0 + ci) * HH + gh) * WW + gw];
            sx[idx] = val;
        }

        // ---- stage weights duplicated: sw2[co][k] = (w,w) ----
        {
            const float4* wg4 = reinterpret_cast<const float4*>(wgt);
#pragma unroll 1
            for (int idx = tid; idx < BC * W4; idx += 256) {
                int co = idx / W4;
                int q  = idx % W4;
                float4 vv = wg4[(((size_t)(co0 + co) * CIN + ci0) * (KS * KS)) / 4 + q];
                ull* dst = &sw2[co * WN + q * 4];
                dst[0] = pk2(vv.x, vv.x);
                dst[1] = pk2(vv.y, vv.y);
                dst[2] = pk2(vv.z, vv.z);
                dst[3] = pk2(vv.w, vv.w);
            }
        }
        __syncthreads();

        // ---- compute ----
#pragma unroll 1
        for (int ci = 0; ci < CC; ci++) {
#pragma unroll
            for (int r = 0; r < KS; r++) {
                const ull* xr8 = reinterpret_cast<const ull*>(
                    &sx[(ci * XROWS + prow + r) * SXW + pcol]);
                if (KS == 3) {
                    ull pA[5], pO[4];
#pragma unroll
                    for (int k = 0; k < 5; k++) pA[k] = xr8[k];      // aligned LDS.64
#pragma unroll
                    for (int k = 0; k < 4; k++) {
                        float2 lo = unpk(pA[k]);
                        float2 hi = unpk(pA[k + 1]);
                        pO[k] = pk2(lo.y, hi.x);                      // odd-shift pairs
                    }
#pragma unroll
                    for (int i = 0; i < 8; i++) {
                        const ull* wp = &sw2[(tc * 8 + i) * WN + ci * 9 + r * 3];
                        ull wv0 = wp[0], wv1 = wp[1], wv2 = wp[2];
#pragma unroll
                        for (int k = 0; k < 4; k++) fma2(acc[i][k], pA[k],     wv0);
#pragma unroll
                        for (int k = 0; k < 4; k++) fma2(acc[i][k], pO[k],     wv1);
#pragma unroll
                        for (int k = 0; k < 4; k++) fma2(acc[i][k], pA[k + 1], wv2);
                    }
                } else {  // KS == 1
                    ull pA[4];
#pragma unroll
                    for (int k = 0; k < 4; k++) pA[k] = xr8[k];
#pragma unroll
                    for (int i = 0; i < 8; i++) {
                        ull wv = sw2[(tc * 8 + i) * WN + ci];
#pragma unroll
                        for (int k = 0; k < 4; k++) fma2(acc[i][k], pA[k], wv);
                    }
                }
            }
        }
    }

    // ---- epilogue: BN (+add) (+relu), vectorized float4 stores ----
    const int hh = h0 + prow;
#pragma unroll
    for (int i = 0; i < 8; i++) {
        const int co = co0 + tc * 8 + i;
        const float sc = scale[co];
        const float bi = bias[co];
        const size_t base = (((size_t)b * COUT + co) * HH + hh) * WW + w0 + pcol;
        float vv[8];
#pragma unroll
        for (int k = 0; k < 4; k++) {
            float2 u = unpk(acc[i][k]);
            vv[2 * k]     = u.x;
            vv[2 * k + 1] = u.y;
        }
#pragma unroll
        for (int j2 = 0; j2 < 2; j2++) {
            float4 o;
            o.x = vv[j2 * 4 + 0] * sc + bi;
            o.y = vv[j2 * 4 + 1] * sc + bi;
            o.z = vv[j2 * 4 + 2] * sc + bi;
            o.w = vv[j2 * 4 + 3] * sc + bi;
            if (ADD) {
                float4 ad = reinterpret_cast<const float4*>(addsrc + base)[j2];
                o.x += ad.x; o.y += ad.y; o.z += ad.z; o.w += ad.w;
            }
            if (RELU) {
                o.x = fmaxf(o.x, 0.f); o.y = fmaxf(o.y, 0.f);
                o.z = fmaxf(o.z, 0.f); o.w = fmaxf(o.w, 0.f);
            }
            reinterpret_cast<float4*>(out + base)[j2] = o;
        }
    }
}

// ---------------------------------------------------------------------------
// Corner pooling part 1: in-place reverse cummax over H on g_p1.
// One thread per (b, c, w) column; coalesced across w.
// ---------------------------------------------------------------------------
__global__ void colscan_kernel(float* __restrict__ p)
{
    int idx = blockIdx.x * blockDim.x + threadIdx.x;   // (b*MID + c)*WW + w
    if (idx >= B_ * MID * WW) return;
    int w  = idx % WW;
    int bc = idx / WW;
    float* col = p + (size_t)bc * HH * WW + w;
    float m = col[(HH - 1) * WW];
#pragma unroll 4
    for (int h = HH - 2; h >= 0; h--) {
        float v = col[h * WW];
        m = fmaxf(m, v);
        col[h * WW] = m;
    }
}

// ---------------------------------------------------------------------------
// Corner pooling part 2: reverse cummax over W of p2 (per row), added into s.
// One 128-thread block per (b, c, h) row; Hillis-Steele suffix-max in smem.
// ---------------------------------------------------------------------------
__global__ void rowscan_add_kernel(const float* __restrict__ p2, float* __restrict__ s)
{
    __shared__ float sm[WW];
    const int t = threadIdx.x;
    const size_t base = (size_t)blockIdx.x * WW;
    sm[t] = p2[base + t];
    __syncthreads();
#pragma unroll
    for (int off = 1; off < WW; off <<= 1) {
        float nv = sm[t];
        if (t + off < WW) nv = fmaxf(nv, sm[t + off]);
        __syncthreads();
        sm[t] = nv;
        __syncthreads();
    }
    s[base + t] += sm[t];
}

// ---------------------------------------------------------------------------
// Launch: p1, p2 -> corner pool -> bn1 -> bn2(+add,relu) -> p3
// ---------------------------------------------------------------------------
extern "C" void kernel_launch(void* const* d_in, const int* in_sizes, int n_in,
                              void* d_out, int out_size)
{
    (void)in_sizes; (void)n_in; (void)out_size;

    const float* x    = (const float*)d_in[0];
    const float* w_p1 = (const float*)d_in[1];
    const float* w_p2 = (const float*)d_in[6];
    const float* w_c1 = (const float*)d_in[11];
    const float* w_c2 = (const float*)d_in[16];
    const float* w_p3 = (const float*)d_in[21];

    float *p1, *p2, *t1, *sc, *bi;
    cudaGetSymbolAddress((void**)&p1, g_p1);
    cudaGetSymbolAddress((void**)&p2, g_p2);
    cudaGetSymbolAddress((void**)&t1, g_t1);
    cudaGetSymbolAddress((void**)&sc, g_scale);
    cudaGetSymbolAddress((void**)&bi, g_bias);

    // Fold all 5 batchnorms (offsets: p1=0, p2=128, c1=256, c2=512, p3=768)
    bn_prep<<<1, 256>>>((const float*)d_in[2],  (const float*)d_in[3],
                        (const float*)d_in[4],  (const float*)d_in[5],  sc + 0,   bi + 0,   MID);
    bn_prep<<<1, 256>>>((const float*)d_in[7],  (const float*)d_in[8],
                        (const float*)d_in[9],  (const float*)d_in[10], sc + 128, bi + 128, MID);
    bn_prep<<<1, 256>>>((const float*)d_in[12], (const float*)d_in[13],
                        (const float*)d_in[14], (const float*)d_in[15], sc + 256, bi + 256, DIM);
    bn_prep<<<1, 256>>>((const float*)d_in[17], (const float*)d_in[18],
                        (const float*)d_in[19], (const float*)d_in[20], sc + 512, bi + 512, DIM);
    bn_prep<<<1, 256>>>((const float*)d_in[22], (const float*)d_in[23],
                        (const float*)d_in[24], (const float*)d_in[25], sc + 768, bi + 768, DIM);

    const int PIX_TILES = B_ * (HH / 4) * (WW / 32);   // 512

    // p1 = relu(bn(conv3x3(x, w_p1)))   [256 -> 128]
    conv_bn<DIM, 3, 4, true, false><<<dim3(PIX_TILES, MID / 128), 256>>>(
        x, w_p1, sc + 0, bi + 0, nullptr, p1, MID);
    // p2 = relu(bn(conv3x3(x, w_p2)))   [256 -> 128]
    conv_bn<DIM, 3, 4, true, false><<<dim3(PIX_TILES, MID / 128), 256>>>(
        x, w_p2, sc + 128, bi + 128, nullptr, p2, MID);

    // corner pooling: p1 <- revcummax_H(p1); p1 += revcummax_W(p2)
    colscan_kernel<<<(B_ * MID * WW + 255) / 256, 256>>>(p1);
    rowscan_add_kernel<<<B_ * MID * HH, WW>>>(p2, p1);

    // t1 = bn(conv3x3(s, w_c1))  (no relu)   [128 -> 256]
    conv_bn<MID, 3, 4, false, false><<<dim3(PIX_TILES, DIM / 128), 256>>>(
        p1, w_c1, sc + 256, bi + 256, nullptr, t1, DIM);

    // t1 = relu(bn(conv1x1(x, w_c2)) + t1)   [256 -> 256], in-place add
    conv_bn<DIM, 1, 16, true, true><<<dim3(PIX_TILES, DIM / 128), 256>>>(
        x, w_c2, sc + 512, bi + 512, t1, t1, DIM);

    // out = relu(bn(conv3x3(r, w_p3)))       [256 -> 256]
    conv_bn<DIM, 3, 4, true, false><<<dim3(PIX_TILES, DIM / 128), 256>>>(
        t1, w_p3, sc + 768, bi + 768, nullptr, (float*)d_out, DIM);
}

// round 10
// speedup vs baseline: 3.6752x; 3.6591x over previous
#include <cuda_runtime.h>
#include <cuda_bf16.h>
#include <cstdint>
#include <cstddef>

using bf16 = __nv_bfloat16;

constexpr int B_  = 4;
constexpr int DIM = 256;
constexpr int MID = 128;
constexpr int HH  = 128;
constexpr int WW  = 128;
constexpr int HW  = HH * WW;

// ------------------------- device scratch -------------------------
__device__ float g_p1[(size_t)B_ * MID * HW];
__device__ float g_p2[(size_t)B_ * MID * HW];
__device__ float g_t1[(size_t)B_ * DIM * HW];
__device__ float g_scale[1024];
__device__ float g_bias[1024];

__device__ bf16 g_xT_hi[(size_t)B_ * HW * DIM];
__device__ bf16 g_xT_lo[(size_t)B_ * HW * DIM];
__device__ bf16 g_sT_hi[(size_t)B_ * HW * MID];
__device__ bf16 g_sT_lo[(size_t)B_ * HW * MID];
__device__ bf16 g_rT_hi[(size_t)B_ * HW * DIM];
__device__ bf16 g_rT_lo[(size_t)B_ * HW * DIM];

constexpr size_t WOFF_P1 = 0;
constexpr size_t WOFF_P2 = WOFF_P1 + (size_t)MID * DIM * 9;
constexpr size_t WOFF_C1 = WOFF_P2 + (size_t)MID * DIM * 9;
constexpr size_t WOFF_C2 = WOFF_C1 + (size_t)DIM * MID * 9;
constexpr size_t WOFF_P3 = WOFF_C2 + (size_t)DIM * DIM * 1;
constexpr size_t WTOT    = WOFF_P3 + (size_t)DIM * DIM * 9;
__device__ bf16 g_w_hi[WTOT];
__device__ bf16 g_w_lo[WTOT];

// ------------------------- helpers (arch-generic: sm_80+ only) -------------------------
__device__ __forceinline__ uint32_t smem_u32(const void* p) {
    uint32_t a;
    asm("{ .reg .u64 t; cvta.to.shared.u64 t, %1; cvt.u32.u64 %0, t; }" : "=r"(a) : "l"(p));
    return a;
}
__device__ __forceinline__ void ldsm4(uint32_t addr, uint32_t* r) {
    asm volatile("ldmatrix.sync.aligned.m8n8.x4.shared.b16 {%0,%1,%2,%3}, [%4];"
                 : "=r"(r[0]), "=r"(r[1]), "=r"(r[2]), "=r"(r[3]) : "r"(addr));
}
__device__ __forceinline__ void mma16816(float* c, const uint32_t* a, uint32_t b0, uint32_t b1) {
    asm volatile("mma.sync.aligned.m16n8k16.row.col.f32.bf16.bf16.f32 "
                 "{%0,%1,%2,%3}, {%4,%5,%6,%7}, {%8,%9}, {%0,%1,%2,%3};"
                 : "+f"(c[0]), "+f"(c[1]), "+f"(c[2]), "+f"(c[3])
                 : "r"(a[0]), "r"(a[1]), "r"(a[2]), "r"(a[3]), "r"(b0), "r"(b1));
}

// ------------------------- prep kernels -------------------------
__global__ void bn_prep(const float* __restrict__ g, const float* __restrict__ b,
                        const float* __restrict__ m, const float* __restrict__ v,
                        float* __restrict__ scale, float* __restrict__ bias, int C)
{
    int i = blockIdx.x * blockDim.x + threadIdx.x;
    if (i < C) {
        float s = g[i] * rsqrtf(v[i] + 1e-5f);
        scale[i] = s;
        bias[i]  = b[i] - m[i] * s;
    }
}

// weights [co][ci][T] f32 -> [tap][co][ci] bf16 hi/lo
__global__ void wsplit(const float* __restrict__ w, bf16* __restrict__ hi,
                       bf16* __restrict__ lo, int COUT, int CIN, int T)
{
    int i = blockIdx.x * 256 + threadIdx.x;
    if (i >= COUT * CIN) return;
    int co = i / CIN, ci = i % CIN;
    for (int t = 0; t < T; t++) {
        float v = w[(size_t)i * T + t];
        bf16 h = __float2bfloat16(v);
        size_t o = ((size_t)t * COUT + co) * CIN + ci;
        hi[o] = h;
        lo[o] = __float2bfloat16(v - __bfloat162float(h));
    }
}

// NCHW f32 -> NHWC bf16 hi/lo. grid (HW/32, C/32, B), block 256
__global__ void split_T(const float* __restrict__ in, bf16* __restrict__ hi,
                        bf16* __restrict__ lo, int C)
{
    __shared__ float t[32][33];
    int pt = blockIdx.x * 32, ct = blockIdx.y * 32, z = blockIdx.z;
    int tx = threadIdx.x & 31, ty = threadIdx.x >> 5;
#pragma unroll
    for (int j = 0; j < 32; j += 8)
        t[ty + j][tx] = in[((size_t)z * C + ct + ty + j) * HW + pt + tx];
    __syncthreads();
#pragma unroll
    for (int j = 0; j < 32; j += 8) {
        float v = t[tx][ty + j];
        bf16 h = __float2bfloat16(v);
        size_t o = ((size_t)z * HW + pt + ty + j) * C + ct + tx;
        hi[o] = h;
        lo[o] = __float2bfloat16(v - __bfloat162float(h));
    }
}

// ------------------------- mma.sync conv -------------------------
// CTA: 128 couts x 64 pixels (half row). 8 warps: 4(M) x 2(N), warp tile 32x32.
// 3x3 taps = +/-1 pixel offsets into halo'd B smem; fp32 register accumulators
// persist across taps+chunks. bf16 2-term split: hh + hl + lh.
template<int CIN, int COUT, int KS, bool RELU, bool ADD>
__global__ __launch_bounds__(256, 2)
void conv_mma(const bf16* __restrict__ xhi, const bf16* __restrict__ xlo,
              const bf16* __restrict__ whi, const bf16* __restrict__ wlo,
              const float* __restrict__ scale, const float* __restrict__ bias,
              const float* __restrict__ addsrc, float* __restrict__ out)
{
    constexpr int SPX   = (KS == 3) ? 66 : 64;   // staged pixels (with halo)
    constexpr int NR    = (KS == 3) ? 3 : 1;     // staged input rows
    constexpr int BPL   = SPX * 128;             // bytes per B plane (one row, one of hi/lo)
    constexpr int ABASE = NR * 2 * BPL;
    constexpr int APL   = 128 * 128;             // A plane: 128 co x 64 ci x 2B

    extern __shared__ char sm[];
    const uint32_t su = smem_u32(sm);

    const int tid = threadIdx.x, wid = tid >> 5, lane = tid & 31;
    const int h  = blockIdx.x & 127, b = blockIdx.x >> 7;
    const int wt = blockIdx.y & 1,  ct = blockIdx.y >> 1;
    const int w0 = wt * 64, co0 = ct * 128;

    const int warpM = wid >> 1, warpN = wid & 1;
    const int mo = warpM * 32;

    float acc[2][4][4];
#pragma unroll
    for (int i = 0; i < 2; i++)
#pragma unroll
        for (int j = 0; j < 4; j++)
#pragma unroll
            for (int k = 0; k < 4; k++) acc[i][j][k] = 0.f;

    for (int ci0 = 0; ci0 < CIN; ci0 += 64) {
        __syncthreads();                       // prior chunk's mma done reading B
        // ---- stage B: NR rows x (hi,lo) x SPX px x 64 ci, swizzled ----
        for (int u = tid; u < NR * 2 * SPX * 8; u += 256) {
            int chunk = u & 7;
            int px    = (u >> 3) % SPX;
            int rp    = (u >> 3) / SPX;        // r*2 + plane
            int plane = rp & 1, r = rp >> 1;
            int hr  = (KS == 3) ? (h - 1 + r) : h;
            int gpx = (KS == 3) ? (w0 - 1 + px) : (w0 + px);
            uint4 v = make_uint4(0, 0, 0, 0);
            if ((unsigned)hr < (unsigned)HH && (unsigned)gpx < (unsigned)WW) {
                const bf16* src = (plane ? xlo : xhi)
                    + ((size_t)((b * HH + hr) * WW + gpx)) * CIN + ci0 + chunk * 8;
                v = *reinterpret_cast<const uint4*>(src);
            }
            *reinterpret_cast<uint4*>(sm + rp * BPL + px * 128 + ((chunk ^ (px & 7)) << 4)) = v;
        }
        for (int tap = 0; tap < KS * KS; tap++) {
            if (tap) __syncthreads();          // prior tap's mma done reading A
            // ---- stage A(tap): 128 co x 64 ci hi/lo, swizzled ----
            for (int u = tid; u < 2048; u += 256) {
                int chunk = u & 7, co = (u >> 3) & 127, plane = u >> 10;
                const bf16* src = (plane ? wlo : whi)
                    + ((size_t)(tap * COUT + co0 + co)) * CIN + ci0 + chunk * 8;
                *reinterpret_cast<uint4*>(sm + ABASE + plane * APL + co * 128
                                          + ((chunk ^ (co & 7)) << 4)) =
                    *reinterpret_cast<const uint4*>(src);
            }
            __syncthreads();

            const int r = tap / KS, s = tap % KS;
            const uint32_t bhB = su + (r * 2 + 0) * BPL;
            const uint32_t blB = su + (r * 2 + 1) * BPL;
            const int sp0 = warpN * 32 + ((KS == 3) ? s : 0);

#pragma unroll
            for (int k = 0; k < 4; k++) {
                uint32_t ah[2][4], al[2][4];
#pragma unroll
                for (int mt = 0; mt < 2; mt++) {
                    int row = mo + mt * 16 + (lane & 15);
                    int ck  = k * 2 + (lane >> 4);
                    uint32_t off = row * 128 + ((ck ^ (row & 7)) << 4);
                    ldsm4(su + ABASE + off, ah[mt]);
                    ldsm4(su + ABASE + APL + off, al[mt]);
                }
                uint32_t bh[2][4], bl[2][4];
#pragma unroll
                for (int np = 0; np < 2; np++) {
                    int px = sp0 + np * 16 + (lane & 7) + ((lane >> 4) << 3);
                    int ck = k * 2 + ((lane >> 3) & 1);
                    uint32_t off = px * 128 + ((ck ^ (px & 7)) << 4);
                    ldsm4(bhB + off, bh[np]);
                    ldsm4(blB + off, bl[np]);
                }
#pragma unroll
                for (int mt = 0; mt < 2; mt++)
#pragma unroll
                    for (int np = 0; np < 2; np++)
#pragma unroll
                        for (int sb = 0; sb < 2; sb++) {
                            float* c = acc[mt][np * 2 + sb];
                            mma16816(c, ah[mt], bh[np][sb * 2], bh[np][sb * 2 + 1]);
                            mma16816(c, ah[mt], bl[np][sb * 2], bl[np][sb * 2 + 1]);
                            mma16816(c, al[mt], bh[np][sb * 2], bh[np][sb * 2 + 1]);
                        }
            }
        }
    }

    // ---- epilogue: BN (+add) (+relu), float2 stores, NCHW f32 ----
    const int g = lane >> 2, q = lane & 3;
#pragma unroll
    for (int mt = 0; mt < 2; mt++) {
#pragma unroll
        for (int half = 0; half < 2; half++) {
            const int co = co0 + mo + mt * 16 + g + half * 8;
            const float sc = scale[co];
            const float bi = bias[co];
            const size_t rowb = ((size_t)(b * COUT + co) * HH + h) * WW;
#pragma unroll
            for (int nt = 0; nt < 4; nt++) {
                const int px = w0 + warpN * 32 + nt * 8 + q * 2;
                float v0 = acc[mt][nt][half * 2 + 0] * sc + bi;
                float v1 = acc[mt][nt][half * 2 + 1] * sc + bi;
                if (ADD) {
                    float2 ad = *reinterpret_cast<const float2*>(addsrc + rowb + px);
                    v0 += ad.x; v1 += ad.y;
                }
                if (RELU) { v0 = fmaxf(v0, 0.f); v1 = fmaxf(v1, 0.f); }
                *reinterpret_cast<float2*>(out + rowb + px) = make_float2(v0, v1);
            }
        }
    }
}

// ------------------------- scans (exact, f32 NCHW) -------------------------
__global__ void colscan_kernel(float* __restrict__ p)
{
    int idx = blockIdx.x * blockDim.x + threadIdx.x;
    if (idx >= B_ * MID * WW) return;
    int w = idx % WW, bc = idx / WW;
    float* col = p + (size_t)bc * HW + w;
    float m = col[(HH - 1) * WW];
#pragma unroll 4
    for (int h = HH - 2; h >= 0; h--) {
        m = fmaxf(m, col[h * WW]);
        col[h * WW] = m;
    }
}
__global__ void rowscan_add_kernel(const float* __restrict__ p2, float* __restrict__ s)
{
    __shared__ float sm[WW];
    const int t = threadIdx.x;
    const size_t base = (size_t)blockIdx.x * WW;
    sm[t] = p2[base + t];
    __syncthreads();
#pragma unroll
    for (int off = 1; off < WW; off <<= 1) {
        float nv = sm[t];
        if (t + off < WW) nv = fmaxf(nv, sm[t + off]);
        __syncthreads();
        sm[t] = nv;
        __syncthreads();
    }
    s[base + t] += sm[t];
}

// ------------------------- launch -------------------------
extern "C" void kernel_launch(void* const* d_in, const int* in_sizes, int n_in,
                              void* d_out, int out_size)
{
    (void)in_sizes; (void)n_in; (void)out_size;

    const float* x = (const float*)d_in[0];

    float *p1, *p2, *t1, *sc, *bi;
    bf16 *xh, *xl, *sh, *sl, *rh, *rl, *wh, *wl;
    cudaGetSymbolAddress((void**)&p1, g_p1);
    cudaGetSymbolAddress((void**)&p2, g_p2);
    cudaGetSymbolAddress((void**)&t1, g_t1);
    cudaGetSymbolAddress((void**)&sc, g_scale);
    cudaGetSymbolAddress((void**)&bi, g_bias);
    cudaGetSymbolAddress((void**)&xh, g_xT_hi);
    cudaGetSymbolAddress((void**)&xl, g_xT_lo);
    cudaGetSymbolAddress((void**)&sh, g_sT_hi);
    cudaGetSymbolAddress((void**)&sl, g_sT_lo);
    cudaGetSymbolAddress((void**)&rh, g_rT_hi);
    cudaGetSymbolAddress((void**)&rl, g_rT_lo);
    cudaGetSymbolAddress((void**)&wh, g_w_hi);
    cudaGetSymbolAddress((void**)&wl, g_w_lo);

    constexpr int SM3 = 6 * 66 * 128 + 2 * 128 * 128;   // 83456
    constexpr int SM1 = 2 * 64 * 128 + 2 * 128 * 128;   // 49152
    cudaFuncSetAttribute(conv_mma<DIM, MID, 3, true,  false>, cudaFuncAttributeMaxDynamicSharedMemorySize, SM3);
    cudaFuncSetAttribute(conv_mma<MID, DIM, 3, false, false>, cudaFuncAttributeMaxDynamicSharedMemorySize, SM3);
    cudaFuncSetAttribute(conv_mma<DIM, DIM, 1, true,  true >, cudaFuncAttributeMaxDynamicSharedMemorySize, SM1);
    cudaFuncSetAttribute(conv_mma<DIM, DIM, 3, true,  false>, cudaFuncAttributeMaxDynamicSharedMemorySize, SM3);

    // BN folding
    bn_prep<<<1, 256>>>((const float*)d_in[2],  (const float*)d_in[3],  (const float*)d_in[4],  (const float*)d_in[5],  sc + 0,   bi + 0,   MID);
    bn_prep<<<1, 256>>>((const float*)d_in[7],  (const float*)d_in[8],  (const float*)d_in[9],  (const float*)d_in[10], sc + 128, bi + 128, MID);
    bn_prep<<<1, 256>>>((const float*)d_in[12], (const float*)d_in[13], (const float*)d_in[14], (const float*)d_in[15], sc + 256, bi + 256, DIM);
    bn_prep<<<1, 256>>>((const float*)d_in[17], (const float*)d_in[18], (const float*)d_in[19], (const float*)d_in[20], sc + 512, bi + 512, DIM);
    bn_prep<<<1, 256>>>((const float*)d_in[22], (const float*)d_in[23], (const float*)d_in[24], (const float*)d_in[25], sc + 768, bi + 768, DIM);

    // weight split (tap-sliced hi/lo)
    wsplit<<<MID * DIM / 256, 256>>>((const float*)d_in[1],  wh + WOFF_P1, wl + WOFF_P1, MID, DIM, 9);
    wsplit<<<MID * DIM / 256, 256>>>((const float*)d_in[6],  wh + WOFF_P2, wl + WOFF_P2, MID, DIM, 9);
    wsplit<<<DIM * MID / 256, 256>>>((const float*)d_in[11], wh + WOFF_C1, wl + WOFF_C1, DIM, MID, 9);
    wsplit<<<DIM * DIM / 256, 256>>>((const float*)d_in[16], wh + WOFF_C2, wl + WOFF_C2, DIM, DIM, 1);
    wsplit<<<DIM * DIM / 256, 256>>>((const float*)d_in[21], wh + WOFF_P3, wl + WOFF_P3, DIM, DIM, 9);

    // x -> NHWC bf16 hi/lo
    split_T<<<dim3(HW / 32, DIM / 32, B_), 256>>>(x, xh, xl, DIM);

    const dim3 G128(B_ * HH, 2), G256(B_ * HH, 4);

    // p1, p2
    conv_mma<DIM, MID, 3, true, false><<<G128, 256, SM3>>>(xh, xl, wh + WOFF_P1, wl + WOFF_P1, sc + 0,   bi + 0,   nullptr, p1);
    conv_mma<DIM, MID, 3, true, false><<<G128, 256, SM3>>>(xh, xl, wh + WOFF_P2, wl + WOFF_P2, sc + 128, bi + 128, nullptr, p2);

    // corner pooling: p1 <- revcummax_H(p1) + revcummax_W(p2)
    colscan_kernel<<<(B_ * MID * WW + 255) / 256, 256>>>(p1);
    rowscan_add_kernel<<<B_ * MID * HH, WW>>>(p2, p1);

    // s -> NHWC hi/lo; c1 (no relu)
    split_T<<<dim3(HW / 32, MID / 32, B_), 256>>>(p1, sh, sl, MID);
    conv_mma<MID, DIM, 3, false, false><<<G256, 256, SM3>>>(sh, sl, wh + WOFF_C1, wl + WOFF_C1, sc + 256, bi + 256, nullptr, t1);

    // c2 1x1 + add + relu -> r (in-place in t1)
    conv_mma<DIM, DIM, 1, true, true><<<G256, 256, SM1>>>(xh, xl, wh + WOFF_C2, wl + WOFF_C2, sc + 512, bi + 512, t1, t1);

    // r -> NHWC hi/lo; p3
    split_T<<<dim3(HW / 32, DIM / 32, B_), 256>>>(t1, rh, rl, DIM);
    conv_mma<DIM, DIM, 3, true, false><<<G256, 256, SM3>>>(rh, rl, wh + WOFF_P3, wl + WOFF_P3, sc + 768, bi + 768, nullptr, (float*)d_out);
}

// round 11
// speedup vs baseline: 4.0942x; 1.1140x over previous
#include <cuda_runtime.h>
#include <cuda_bf16.h>
#include <cstdint>
#include <cstddef>

using bf16 = __nv_bfloat16;

constexpr int B_  = 4;
constexpr int DIM = 256;
constexpr int MID = 128;
constexpr int HH  = 128;
constexpr int WW  = 128;
constexpr int HW  = HH * WW;

// ------------------------- device scratch -------------------------
__device__ float g_p1[(size_t)B_ * MID * HW];
__device__ float g_p2[(size_t)B_ * MID * HW];
__device__ float g_t1[(size_t)B_ * DIM * HW];
__device__ float g_scale[1024];
__device__ float g_bias[1024];

__device__ bf16 g_xT_hi[(size_t)B_ * HW * DIM];
__device__ bf16 g_xT_lo[(size_t)B_ * HW * DIM];
__device__ bf16 g_sT_hi[(size_t)B_ * HW * MID];
__device__ bf16 g_sT_lo[(size_t)B_ * HW * MID];
__device__ bf16 g_rT_hi[(size_t)B_ * HW * DIM];
__device__ bf16 g_rT_lo[(size_t)B_ * HW * DIM];

constexpr size_t WOFF_P1 = 0;
constexpr size_t WOFF_P2 = WOFF_P1 + (size_t)MID * DIM * 9;
constexpr size_t WOFF_C1 = WOFF_P2 + (size_t)MID * DIM * 9;
constexpr size_t WOFF_C2 = WOFF_C1 + (size_t)DIM * MID * 9;
constexpr size_t WOFF_P3 = WOFF_C2 + (size_t)DIM * DIM * 1;
constexpr size_t WTOT    = WOFF_P3 + (size_t)DIM * DIM * 9;
__device__ bf16 g_w_hi[WTOT];
__device__ bf16 g_w_lo[WTOT];

// ------------------------- helpers (sm_80+ generic) -------------------------
__device__ __forceinline__ uint32_t smem_u32(const void* p) {
    uint32_t a;
    asm("{ .reg .u64 t; cvta.to.shared.u64 t, %1; cvt.u32.u64 %0, t; }" : "=r"(a) : "l"(p));
    return a;
}
__device__ __forceinline__ void ldsm4(uint32_t addr, uint32_t* r) {
    asm volatile("ldmatrix.sync.aligned.m8n8.x4.shared.b16 {%0,%1,%2,%3}, [%4];"
                 : "=r"(r[0]), "=r"(r[1]), "=r"(r[2]), "=r"(r[3]) : "r"(addr));
}
__device__ __forceinline__ void mma16816(float* c, const uint32_t* a, uint32_t b0, uint32_t b1) {
    asm volatile("mma.sync.aligned.m16n8k16.row.col.f32.bf16.bf16.f32 "
                 "{%0,%1,%2,%3}, {%4,%5,%6,%7}, {%8,%9}, {%0,%1,%2,%3};"
                 : "+f"(c[0]), "+f"(c[1]), "+f"(c[2]), "+f"(c[3])
                 : "r"(a[0]), "r"(a[1]), "r"(a[2]), "r"(a[3]), "r"(b0), "r"(b1));
}
__device__ __forceinline__ void cpa16(uint32_t dst, const void* src) {
    asm volatile("cp.async.cg.shared.global [%0], [%1], 16;" :: "r"(dst), "l"(src) : "memory");
}
__device__ __forceinline__ void cpa_commit() { asm volatile("cp.async.commit_group;" ::: "memory"); }
__device__ __forceinline__ void cpa_wait0()  { asm volatile("cp.async.wait_group 0;" ::: "memory"); }

// ------------------------- prep kernels -------------------------
__global__ void bn_prep(const float* __restrict__ g, const float* __restrict__ b,
                        const float* __restrict__ m, const float* __restrict__ v,
                        float* __restrict__ scale, float* __restrict__ bias, int C)
{
    int i = blockIdx.x * blockDim.x + threadIdx.x;
    if (i < C) {
        float s = g[i] * rsqrtf(v[i] + 1e-5f);
        scale[i] = s;
        bias[i]  = b[i] - m[i] * s;
    }
}

// weights [co][ci][T] f32 -> [tap][co][ci] bf16 hi/lo
__global__ void wsplit(const float* __restrict__ w, bf16* __restrict__ hi,
                       bf16* __restrict__ lo, int COUT, int CIN, int T)
{
    int i = blockIdx.x * 256 + threadIdx.x;
    if (i >= COUT * CIN) return;
    int co = i / CIN, ci = i % CIN;
    for (int t = 0; t < T; t++) {
        float v = w[(size_t)i * T + t];
        bf16 h = __float2bfloat16(v);
        size_t o = ((size_t)t * COUT + co) * CIN + ci;
        hi[o] = h;
        lo[o] = __float2bfloat16(v - __bfloat162float(h));
    }
}

// NCHW f32 -> NHWC bf16 hi/lo. grid (HW/32, C/32, B), block 256
__global__ void split_T(const float* __restrict__ in, bf16* __restrict__ hi,
                        bf16* __restrict__ lo, int C)
{
    __shared__ float t[32][33];
    int pt = blockIdx.x * 32, ct = blockIdx.y * 32, z = blockIdx.z;
    int tx = threadIdx.x & 31, ty = threadIdx.x >> 5;
#pragma unroll
    for (int j = 0; j < 32; j += 8)
        t[ty + j][tx] = in[((size_t)z * C + ct + ty + j) * HW + pt + tx];
    __syncthreads();
#pragma unroll
    for (int j = 0; j < 32; j += 8) {
        float v = t[tx][ty + j];
        bf16 h = __float2bfloat16(v);
        size_t o = ((size_t)z * HW + pt + ty + j) * C + ct + tx;
        hi[o] = h;
        lo[o] = __float2bfloat16(v - __bfloat162float(h));
    }
}

// ------------------------- mma.sync conv (full-row tile) -------------------------
// CTA: 128 couts x 128 pixels (one image row). 8 warps: 4(M) x 2(N),
// warp tile 32co x 64px, 64 fp32 acc/thread. K chunk = 64 ci.
// A (weights) double-buffered via cp.async across the tap sequence.
// bf16 2-term split: hh + hl + lh into the same accumulators.
template<int CIN, int COUT, int KS, bool RELU, bool ADD>
__global__ __launch_bounds__(256, 1)
void conv_mma(const bf16* __restrict__ xhi, const bf16* __restrict__ xlo,
              const bf16* __restrict__ whi, const bf16* __restrict__ wlo,
              const float* __restrict__ scale, const float* __restrict__ bias,
              const float* __restrict__ addsrc, float* __restrict__ out)
{
    constexpr int SPX   = (KS == 3) ? 130 : 128;   // staged pixels (halo)
    constexpr int NR    = (KS == 3) ? 3 : 1;       // staged input rows
    constexpr int BPL   = SPX * 128;               // bytes per B plane
    constexpr int ABASE = NR * 2 * BPL;
    constexpr int ABUF  = 32768;                   // one A buffer (hi+lo)
    constexpr int NT    = KS * KS;
    constexpr int NC    = CIN / 64;

    extern __shared__ char sm[];
    const uint32_t su = smem_u32(sm);

    const int tid = threadIdx.x, wid = tid >> 5, lane = tid & 31;
    const int h  = blockIdx.x & 127, b = blockIdx.x >> 7;
    const int co0 = blockIdx.y << 7;

    const int warpM = wid >> 1, warpN = wid & 1;
    const int mo = warpM * 32;

    float acc[2][8][4];
#pragma unroll
    for (int i = 0; i < 2; i++)
#pragma unroll
        for (int j = 0; j < 8; j++)
#pragma unroll
            for (int k = 0; k < 4; k++) acc[i][j][k] = 0.f;

    // ---- A staging (cp.async into ping-pong buffer) ----
    auto stage_A = [&](int tap, int ci0, int buf) {
#pragma unroll
        for (int it = 0; it < 8; it++) {
            int u = tid + it * 256;
            int chunk = u & 7, co = (u >> 3) & 127, plane = u >> 10;
            const bf16* src = (plane ? wlo : whi)
                + ((size_t)(tap * COUT + co0 + co)) * CIN + ci0 + chunk * 8;
            cpa16(su + ABASE + buf * ABUF + plane * 16384 + co * 128
                      + ((chunk ^ (co & 7)) << 4), src);
        }
        cpa_commit();
    };

    // ---- B staging: NR rows x 2 planes x SPX px x 64 ci, OOB zero-filled ----
    auto stage_B = [&](int ci0) {
        constexpr int ITEMS = NR * 2 * SPX * 8;
        for (int u = tid; u < ITEMS; u += 256) {
            int chunk = u & 7;
            int px    = (u >> 3) % SPX;
            int rp    = (u >> 3) / SPX;
            int plane = rp & 1, r = rp >> 1;
            int hr  = (KS == 3) ? (h - 1 + r) : h;
            int gpx = (KS == 3) ? (px - 1) : px;
            uint32_t doff = rp * BPL + px * 128 + ((chunk ^ (px & 7)) << 4);
            if ((unsigned)hr < (unsigned)HH && (unsigned)gpx < (unsigned)WW) {
                const bf16* src = (plane ? xlo : xhi)
                    + ((size_t)((b * HH + hr) * WW + gpx)) * CIN + ci0 + chunk * 8;
                cpa16(su + doff, src);
            } else {
                *reinterpret_cast<uint4*>(sm + doff) = make_uint4(0, 0, 0, 0);
            }
        }
        cpa_commit();
    };

    stage_A(0, 0, 0);                         // prologue prefetch

    for (int c = 0; c < NC; c++) {
        stage_B(c * 64);
        cpa_wait0();
        __syncthreads();
#pragma unroll 1
        for (int t = 0; t < NT; t++) {
            const int seq = c * NT + t;
            const int nxt = seq + 1;
            if (nxt < NC * NT)
                stage_A(nxt % NT, (nxt / NT) * 64, nxt & 1);

            const uint32_t Ab  = su + ABASE + (seq & 1) * ABUF;
            const int r = t / KS, s = t % KS;
            const uint32_t bhB = su + (r * 2 + 0) * BPL;
            const uint32_t blB = su + (r * 2 + 1) * BPL;
            const int sp0 = warpN * 64 + ((KS == 3) ? s : 0);

#pragma unroll
            for (int k = 0; k < 4; k++) {
                uint32_t ah[2][4], al[2][4];
#pragma unroll
                for (int mt = 0; mt < 2; mt++) {
                    int row = mo + mt * 16 + (lane & 15);
                    int ck  = k * 2 + (lane >> 4);
                    uint32_t off = row * 128 + ((ck ^ (row & 7)) << 4);
                    ldsm4(Ab + off, ah[mt]);
                    ldsm4(Ab + 16384 + off, al[mt]);
                }
#pragma unroll
                for (int np = 0; np < 4; np++) {
                    uint32_t bh[4], bl[4];
                    int px = sp0 + np * 16 + (lane & 7) + ((lane >> 4) << 3);
                    int ck = k * 2 + ((lane >> 3) & 1);
                    uint32_t off = px * 128 + ((ck ^ (px & 7)) << 4);
                    ldsm4(bhB + off, bh);
                    ldsm4(blB + off, bl);
#pragma unroll
                    for (int mt = 0; mt < 2; mt++)
#pragma unroll
                        for (int sb = 0; sb < 2; sb++) {
                            float* cc = acc[mt][np * 2 + sb];
                            mma16816(cc, ah[mt], bh[sb * 2], bh[sb * 2 + 1]);
                            mma16816(cc, ah[mt], bl[sb * 2], bl[sb * 2 + 1]);
                            mma16816(cc, al[mt], bh[sb * 2], bh[sb * 2 + 1]);
                        }
                }
            }
            cpa_wait0();
            __syncthreads();
        }
    }

    // ---- epilogue: BN (+add) (+relu), float2 stores, NCHW f32 ----
    const int g = lane >> 2, q = lane & 3;
#pragma unroll
    for (int mt = 0; mt < 2; mt++) {
#pragma unroll
        for (int half = 0; half < 2; half++) {
            const int co = co0 + mo + mt * 16 + g + half * 8;
            const float sc = scale[co];
            const float bi = bias[co];
            const size_t rowb = ((size_t)(b * COUT + co) * HH + h) * WW;
#pragma unroll
            for (int nt = 0; nt < 8; nt++) {
                const int px = warpN * 64 + nt * 8 + q * 2;
                float v0 = acc[mt][nt][half * 2 + 0] * sc + bi;
                float v1 = acc[mt][nt][half * 2 + 1] * sc + bi;
                if (ADD) {
                    float2 ad = *reinterpret_cast<const float2*>(addsrc + rowb + px);
                    v0 += ad.x; v1 += ad.y;
                }
                if (RELU) { v0 = fmaxf(v0, 0.f); v1 = fmaxf(v1, 0.f); }
                *reinterpret_cast<float2*>(out + rowb + px) = make_float2(v0, v1);
            }
        }
    }
}

// ------------------------- scans (exact, f32 NCHW) -------------------------
__global__ void colscan_kernel(float* __restrict__ p)
{
    int idx = blockIdx.x * blockDim.x + threadIdx.x;
    if (idx >= B_ * MID * WW) return;
    int w = idx % WW, bc = idx / WW;
    float* col = p + (size_t)bc * HW + w;
    float m = col[(HH - 1) * WW];
#pragma unroll 4
    for (int h = HH - 2; h >= 0; h--) {
        m = fmaxf(m, col[h * WW]);
        col[h * WW] = m;
    }
}
__global__ void rowscan_add_kernel(const float* __restrict__ p2, float* __restrict__ s)
{
    __shared__ float sm[WW];
    const int t = threadIdx.x;
    const size_t base = (size_t)blockIdx.x * WW;
    sm[t] = p2[base + t];
    __syncthreads();
#pragma unroll
    for (int off = 1; off < WW; off <<= 1) {
        float nv = sm[t];
        if (t + off < WW) nv = fmaxf(nv, sm[t + off]);
        __syncthreads();
        sm[t] = nv;
        __syncthreads();
    }
    s[base + t] += sm[t];
}

// ------------------------- launch -------------------------
extern "C" void kernel_launch(void* const* d_in, const int* in_sizes, int n_in,
                              void* d_out, int out_size)
{
    (void)in_sizes; (void)n_in; (void)out_size;

    const float* x = (const float*)d_in[0];

    float *p1, *p2, *t1, *sc, *bi;
    bf16 *xh, *xl, *sh, *sl, *rh, *rl, *wh, *wl;
    cudaGetSymbolAddress((void**)&p1, g_p1);
    cudaGetSymbolAddress((void**)&p2, g_p2);
    cudaGetSymbolAddress((void**)&t1, g_t1);
    cudaGetSymbolAddress((void**)&sc, g_scale);
    cudaGetSymbolAddress((void**)&bi, g_bias);
    cudaGetSymbolAddress((void**)&xh, g_xT_hi);
    cudaGetSymbolAddress((void**)&xl, g_xT_lo);
    cudaGetSymbolAddress((void**)&sh, g_sT_hi);
    cudaGetSymbolAddress((void**)&sl, g_sT_lo);
    cudaGetSymbolAddress((void**)&rh, g_rT_hi);
    cudaGetSymbolAddress((void**)&rl, g_rT_lo);
    cudaGetSymbolAddress((void**)&wh, g_w_hi);
    cudaGetSymbolAddress((void**)&wl, g_w_lo);

    constexpr int SM3 = 6 * 130 * 128 + 2 * 32768;   // 165376
    constexpr int SM1 = 2 * 128 * 128 + 2 * 32768;   // 98304
    cudaFuncSetAttribute(conv_mma<DIM, MID, 3, true,  false>, cudaFuncAttributeMaxDynamicSharedMemorySize, SM3);
    cudaFuncSetAttribute(conv_mma<MID, DIM, 3, false, false>, cudaFuncAttributeMaxDynamicSharedMemorySize, SM3);
    cudaFuncSetAttribute(conv_mma<DIM, DIM, 1, true,  true >, cudaFuncAttributeMaxDynamicSharedMemorySize, SM1);
    cudaFuncSetAttribute(conv_mma<DIM, DIM, 3, true,  false>, cudaFuncAttributeMaxDynamicSharedMemorySize, SM3);

    // BN folding
    bn_prep<<<1, 256>>>((const float*)d_in[2],  (const float*)d_in[3],  (const float*)d_in[4],  (const float*)d_in[5],  sc + 0,   bi + 0,   MID);
    bn_prep<<<1, 256>>>((const float*)d_in[7],  (const float*)d_in[8],  (const float*)d_in[9],  (const float*)d_in[10], sc + 128, bi + 128, MID);
    bn_prep<<<1, 256>>>((const float*)d_in[12], (const float*)d_in[13], (const float*)d_in[14], (const float*)d_in[15], sc + 256, bi + 256, DIM);
    bn_prep<<<1, 256>>>((const float*)d_in[17], (const float*)d_in[18], (const float*)d_in[19], (const float*)d_in[20], sc + 512, bi + 512, DIM);
    bn_prep<<<1, 256>>>((const float*)d_in[22], (const float*)d_in[23], (const float*)d_in[24], (const float*)d_in[25], sc + 768, bi + 768, DIM);

    // weight split (tap-sliced hi/lo)
    wsplit<<<MID * DIM / 256, 256>>>((const float*)d_in[1],  wh + WOFF_P1, wl + WOFF_P1, MID, DIM, 9);
    wsplit<<<MID * DIM / 256, 256>>>((const float*)d_in[6],  wh + WOFF_P2, wl + WOFF_P2, MID, DIM, 9);
    wsplit<<<DIM * MID / 256, 256>>>((const float*)d_in[11], wh + WOFF_C1, wl + WOFF_C1, DIM, MID, 9);
    wsplit<<<DIM * DIM / 256, 256>>>((const float*)d_in[16], wh + WOFF_C2, wl + WOFF_C2, DIM, DIM, 1);
    wsplit<<<DIM * DIM / 256, 256>>>((const float*)d_in[21], wh + WOFF_P3, wl + WOFF_P3, DIM, DIM, 9);

    // x -> NHWC bf16 hi/lo
    split_T<<<dim3(HW / 32, DIM / 32, B_), 256>>>(x, xh, xl, DIM);

    const dim3 G1(B_ * HH, 1), G2(B_ * HH, 2);

    // p1, p2
    conv_mma<DIM, MID, 3, true, false><<<G1, 256, SM3>>>(xh, xl, wh + WOFF_P1, wl + WOFF_P1, sc + 0,   bi + 0,   nullptr, p1);
    conv_mma<DIM, MID, 3, true, false><<<G1, 256, SM3>>>(xh, xl, wh + WOFF_P2, wl + WOFF_P2, sc + 128, bi + 128, nullptr, p2);

    // corner pooling: p1 <- revcummax_H(p1) + revcummax_W(p2)
    colscan_kernel<<<(B_ * MID * WW + 255) / 256, 256>>>(p1);
    rowscan_add_kernel<<<B_ * MID * HH, WW>>>(p2, p1);

    // s -> NHWC hi/lo; c1 (no relu)
    split_T<<<dim3(HW / 32, MID / 32, B_), 256>>>(p1, sh, sl, MID);
    conv_mma<MID, DIM, 3, false, false><<<G2, 256, SM3>>>(sh, sl, wh + WOFF_C1, wl + WOFF_C1, sc + 256, bi + 256, nullptr, t1);

    // c2 1x1 + add + relu -> r (in-place in t1)
    conv_mma<DIM, DIM, 1, true, true><<<G2, 256, SM1>>>(xh, xl, wh + WOFF_C2, wl + WOFF_C2, sc + 512, bi + 512, t1, t1);

    // r -> NHWC hi/lo; p3
    split_T<<<dim3(HW / 32, DIM / 32, B_), 256>>>(t1, rh, rl, DIM);
    conv_mma<DIM, DIM, 3, true, false><<<G2, 256, SM3>>>(rh, rl, wh + WOFF_P3, wl + WOFF_P3, sc + 768, bi + 768, nullptr, (float*)d_out);
}

// round 12
// speedup vs baseline: 4.3876x; 1.0717x over previous
#include <cuda_runtime.h>
#include <cuda_bf16.h>
#include <cstdint>
#include <cstddef>

using bf16 = __nv_bfloat16;

constexpr int B_  = 4;
constexpr int DIM = 256;
constexpr int MID = 128;
constexpr int HH  = 128;
constexpr int WW  = 128;
constexpr int HW  = HH * WW;

// ------------------------- device scratch -------------------------
__device__ float g_p1[(size_t)B_ * MID * HW];
__device__ float g_p2[(size_t)B_ * MID * HW];
__device__ float g_t1[(size_t)B_ * DIM * HW];      // r
__device__ float g_scale[1024];
__device__ float g_bias[1024];

__device__ bf16 g_xT_hi[(size_t)B_ * HW * DIM];
__device__ bf16 g_xT_lo[(size_t)B_ * HW * DIM];
__device__ bf16 g_sT_hi[(size_t)B_ * HW * MID];
__device__ bf16 g_sT_lo[(size_t)B_ * HW * MID];
__device__ bf16 g_rT_hi[(size_t)B_ * HW * DIM];
__device__ bf16 g_rT_lo[(size_t)B_ * HW * DIM];

constexpr size_t WOFF_P1 = 0;
constexpr size_t WOFF_P2 = WOFF_P1 + (size_t)MID * DIM * 9;
constexpr size_t WOFF_C1 = WOFF_P2 + (size_t)MID * DIM * 9;
constexpr size_t WOFF_C2 = WOFF_C1 + (size_t)DIM * MID * 9;
constexpr size_t WOFF_P3 = WOFF_C2 + (size_t)DIM * DIM * 1;
constexpr size_t WTOT    = WOFF_P3 + (size_t)DIM * DIM * 9;
__device__ bf16 g_w_hi[WTOT];
__device__ bf16 g_w_lo[WTOT];

// ------------------------- helpers (sm_80+ generic) -------------------------
__device__ __forceinline__ uint32_t smem_u32(const void* p) {
    uint32_t a;
    asm("{ .reg .u64 t; cvta.to.shared.u64 t, %1; cvt.u32.u64 %0, t; }" : "=r"(a) : "l"(p));
    return a;
}
__device__ __forceinline__ void ldsm4(uint32_t addr, uint32_t* r) {
    asm volatile("ldmatrix.sync.aligned.m8n8.x4.shared.b16 {%0,%1,%2,%3}, [%4];"
                 : "=r"(r[0]), "=r"(r[1]), "=r"(r[2]), "=r"(r[3]) : "r"(addr));
}
__device__ __forceinline__ void mma16816(float* c, const uint32_t* a, uint32_t b0, uint32_t b1) {
    asm volatile("mma.sync.aligned.m16n8k16.row.col.f32.bf16.bf16.f32 "
                 "{%0,%1,%2,%3}, {%4,%5,%6,%7}, {%8,%9}, {%0,%1,%2,%3};"
                 : "+f"(c[0]), "+f"(c[1]), "+f"(c[2]), "+f"(c[3])
                 : "r"(a[0]), "r"(a[1]), "r"(a[2]), "r"(a[3]), "r"(b0), "r"(b1));
}
__device__ __forceinline__ void cpa16(uint32_t dst, const void* src) {
    asm volatile("cp.async.cg.shared.global [%0], [%1], 16;" :: "r"(dst), "l"(src) : "memory");
}
__device__ __forceinline__ void cpa_commit() { asm volatile("cp.async.commit_group;" ::: "memory"); }
__device__ __forceinline__ void cpa_wait0()  { asm volatile("cp.async.wait_group 0;" ::: "memory"); }

// ------------------------- prep kernels -------------------------
__global__ void bn_prep(const float* __restrict__ g, const float* __restrict__ b,
                        const float* __restrict__ m, const float* __restrict__ v,
                        float* __restrict__ scale, float* __restrict__ bias, int C)
{
    int i = blockIdx.x * blockDim.x + threadIdx.x;
    if (i < C) {
        float s = g[i] * rsqrtf(v[i] + 1e-5f);
        scale[i] = s;
        bias[i]  = b[i] - m[i] * s;
    }
}

// weights [co][ci][T] f32, BN-scale folded -> [tap][co][ci] bf16 hi/lo
__global__ void wsplit(const float* __restrict__ w, const float* __restrict__ scale,
                       bf16* __restrict__ hi, bf16* __restrict__ lo,
                       int COUT, int CIN, int T)
{
    int i = blockIdx.x * 256 + threadIdx.x;
    if (i >= COUT * CIN) return;
    int co = i / CIN, ci = i % CIN;
    float sc = scale[co];
    for (int t = 0; t < T; t++) {
        float v = w[(size_t)i * T + t] * sc;
        bf16 h = __float2bfloat16(v);
        size_t o = ((size_t)t * COUT + co) * CIN + ci;
        hi[o] = h;
        lo[o] = __float2bfloat16(v - __bfloat162float(h));
    }
}

// NCHW f32 -> NHWC bf16 hi/lo. grid (HW/32, C/32, B), block 256
__global__ void split_T(const float* __restrict__ in, bf16* __restrict__ hi,
                        bf16* __restrict__ lo, int C)
{
    __shared__ float t[32][33];
    int pt = blockIdx.x * 32, ct = blockIdx.y * 32, z = blockIdx.z;
    int tx = threadIdx.x & 31, ty = threadIdx.x >> 5;
#pragma unroll
    for (int j = 0; j < 32; j += 8)
        t[ty + j][tx] = in[((size_t)z * C + ct + ty + j) * HW + pt + tx];
    __syncthreads();
#pragma unroll
    for (int j = 0; j < 32; j += 8) {
        float v = t[tx][ty + j];
        bf16 h = __float2bfloat16(v);
        size_t o = ((size_t)z * HW + pt + ty + j) * C + ct + tx;
        hi[o] = h;
        lo[o] = __float2bfloat16(v - __bfloat162float(h));
    }
}

// ===================== generic 3x3 conv, CIN=256 ==========================
// CTA: 128 couts x 128 pixels (one image row). 8 warps: 4(M) x 2(N),
// warp tile 32co x 64px. BN scale folded into weights; epilogue relu(acc+bias).
// DUAL: blockIdx.y selects {w,out,bias} set (p1/p2 batched). else y = co-tile.
template<bool DUAL>
__global__ __launch_bounds__(256, 1)
void conv3(const bf16* __restrict__ xhi, const bf16* __restrict__ xlo,
           const bf16* __restrict__ wh0, const bf16* __restrict__ wl0,
           const bf16* __restrict__ wh1, const bf16* __restrict__ wl1,
           const float* __restrict__ bias0, const float* __restrict__ bias1,
           float* __restrict__ out0, float* __restrict__ out1, int COUT)
{
    constexpr int CIN = 256;
    constexpr int SPX = 130, BPL = SPX * 128;
    constexpr int ABASE = 6 * BPL;
    constexpr int ABUF  = 32768;

    extern __shared__ char sm[];
    const uint32_t su = smem_u32(sm);

    const int tid = threadIdx.x, wid = tid >> 5, lane = tid & 31;
    const int h  = blockIdx.x & 127, b = blockIdx.x >> 7;
    const int y  = blockIdx.y;
    const int co0 = DUAL ? 0 : (y << 7);
    const bf16* wh = (DUAL && y) ? wh1 : wh0;
    const bf16* wl = (DUAL && y) ? wl1 : wl0;
    const float* bias = (DUAL && y) ? bias1 : bias0;
    float* out = (DUAL && y) ? out1 : out0;

    const int warpM = wid >> 1, warpN = wid & 1;
    const int mo = warpM * 32;

    float acc[2][8][4];
#pragma unroll
    for (int i = 0; i < 2; i++)
#pragma unroll
        for (int j = 0; j < 8; j++)
#pragma unroll
            for (int k = 0; k < 4; k++) acc[i][j][k] = 0.f;

    auto stage_A = [&](int tap, int ci0, int buf) {
#pragma unroll
        for (int it = 0; it < 8; it++) {
            int u = tid + it * 256;
            int chunk = u & 7, co = (u >> 3) & 127, plane = u >> 10;
            const bf16* src = (plane ? wl : wh)
                + ((size_t)(tap * COUT + co0 + co)) * CIN + ci0 + chunk * 8;
            cpa16(su + ABASE + buf * ABUF + plane * 16384 + co * 128
                      + ((chunk ^ (co & 7)) << 4), src);
        }
        cpa_commit();
    };
    auto stage_B = [&](int ci0) {
        for (int u = tid; u < 6 * SPX * 8; u += 256) {
            int chunk = u & 7;
            int px    = (u >> 3) % SPX;
            int rp    = (u >> 3) / SPX;
            int plane = rp & 1, r = rp >> 1;
            int hr = h - 1 + r, gpx = px - 1;
            uint32_t doff = rp * BPL + px * 128 + ((chunk ^ (px & 7)) << 4);
            if ((unsigned)hr < (unsigned)HH && (unsigned)gpx < (unsigned)WW) {
                const bf16* src = (plane ? xlo : xhi)
                    + ((size_t)((b * HH + hr) * WW + gpx)) * CIN + ci0 + chunk * 8;
                cpa16(su + doff, src);
            } else {
                *reinterpret_cast<uint4*>(sm + doff) = make_uint4(0, 0, 0, 0);
            }
        }
        cpa_commit();
    };

    stage_A(0, 0, 0);
    for (int c = 0; c < 4; c++) {
        stage_B(c * 64);
        cpa_wait0();
        __syncthreads();
#pragma unroll 1
        for (int t = 0; t < 9; t++) {
            const int seq = c * 9 + t, nxt = seq + 1;
            if (nxt < 36) stage_A(nxt % 9, (nxt / 9) * 64, nxt & 1);

            const uint32_t Ab  = su + ABASE + (seq & 1) * ABUF;
            const int r = t / 3, s = t % 3;
            const uint32_t bhB = su + (r * 2 + 0) * BPL;
            const uint32_t blB = su + (r * 2 + 1) * BPL;
            const int sp0 = warpN * 64 + s;

#pragma unroll
            for (int k = 0; k < 4; k++) {
                uint32_t ah[2][4], al[2][4];
#pragma unroll
                for (int mt = 0; mt < 2; mt++) {
                    int row = mo + mt * 16 + (lane & 15);
                    int ck  = k * 2 + (lane >> 4);
                    uint32_t off = row * 128 + ((ck ^ (row & 7)) << 4);
                    ldsm4(Ab + off, ah[mt]);
                    ldsm4(Ab + 16384 + off, al[mt]);
                }
#pragma unroll
                for (int np = 0; np < 4; np++) {
                    uint32_t bh[4], bl[4];
                    int px = sp0 + np * 16 + (lane & 7) + ((lane >> 4) << 3);
                    int ck = k * 2 + ((lane >> 3) & 1);
                    uint32_t off = px * 128 + ((ck ^ (px & 7)) << 4);
                    ldsm4(bhB + off, bh);
                    ldsm4(blB + off, bl);
#pragma unroll
                    for (int mt = 0; mt < 2; mt++)
#pragma unroll
                        for (int sb = 0; sb < 2; sb++) {
                            float* cc = acc[mt][np * 2 + sb];
                            mma16816(cc, ah[mt], bh[sb * 2], bh[sb * 2 + 1]);
                            mma16816(cc, ah[mt], bl[sb * 2], bl[sb * 2 + 1]);
                            mma16816(cc, al[mt], bh[sb * 2], bh[sb * 2 + 1]);
                        }
                }
            }
            cpa_wait0();
            __syncthreads();
        }
    }

    const int g = lane >> 2, q = lane & 3;
#pragma unroll
    for (int mt = 0; mt < 2; mt++)
#pragma unroll
        for (int half = 0; half < 2; half++) {
            const int co = co0 + mo + mt * 16 + g + half * 8;
            const float bi = bias[co];
            const size_t rowb = ((size_t)(b * COUT + co) * HH + h) * WW;
#pragma unroll
            for (int nt = 0; nt < 8; nt++) {
                const int px = warpN * 64 + nt * 8 + q * 2;
                float v0 = fmaxf(acc[mt][nt][half * 2 + 0] + bi, 0.f);
                float v1 = fmaxf(acc[mt][nt][half * 2 + 1] + bi, 0.f);
                *reinterpret_cast<float2*>(out + rowb + px) = make_float2(v0, v1);
            }
        }
}

// ===================== fused c1(3x3 over s) + c2(1x1 over x) ==============
// r = relu( conv3x3(s, w_c1*sc1) + conv1x1(x, w_c2*sc2) + b1 + b2 )
// Phase 1: 2 K-chunks of s (CIN=128) x 9 taps.  Phase 2: 4 K-chunks of x (CIN=256).
__global__ __launch_bounds__(256, 1)
void conv_c1c2(const bf16* __restrict__ shi, const bf16* __restrict__ slo,
               const bf16* __restrict__ xhi, const bf16* __restrict__ xlo,
               const bf16* __restrict__ wh1, const bf16* __restrict__ wl1,
               const bf16* __restrict__ wh2, const bf16* __restrict__ wl2,
               const float* __restrict__ b1, const float* __restrict__ b2,
               float* __restrict__ out)
{
    constexpr int COUT = 256;
    constexpr int SPX = 130, BPL = SPX * 128;
    constexpr int ABASE = 6 * BPL;
    constexpr int ABUF  = 32768;

    extern __shared__ char sm[];
    const uint32_t su = smem_u32(sm);

    const int tid = threadIdx.x, wid = tid >> 5, lane = tid & 31;
    const int h  = blockIdx.x & 127, b = blockIdx.x >> 7;
    const int co0 = blockIdx.y << 7;
    const int warpM = wid >> 1, warpN = wid & 1;
    const int mo = warpM * 32;

    float acc[2][8][4];
#pragma unroll
    for (int i = 0; i < 2; i++)
#pragma unroll
        for (int j = 0; j < 8; j++)
#pragma unroll
            for (int k = 0; k < 4; k++) acc[i][j][k] = 0.f;

    // seq 0..17: c1 (tap=seq%9, chunk=seq/9, CIN=128); seq 18..21: c2 (chunk=seq-18, CIN=256)
    auto stage_A = [&](int seq, int buf) {
#pragma unroll
        for (int it = 0; it < 8; it++) {
            int u = tid + it * 256;
            int chunk = u & 7, co = (u >> 3) & 127, plane = u >> 10;
            const bf16* src;
            if (seq < 18) {
                int tap = seq % 9, ch = seq / 9;
                src = (plane ? wl1 : wh1)
                    + ((size_t)(tap * COUT + co0 + co)) * 128 + ch * 64 + chunk * 8;
            } else {
                int ch = seq - 18;
                src = (plane ? wl2 : wh2)
                    + ((size_t)(co0 + co)) * 256 + ch * 64 + chunk * 8;
            }
            cpa16(su + ABASE + buf * ABUF + plane * 16384 + co * 128
                      + ((chunk ^ (co & 7)) << 4), src);
        }
        cpa_commit();
    };
    auto stage_B1 = [&](int ci0) {           // s rows h-1..h+1, halo, CIN=128
        for (int u = tid; u < 6 * SPX * 8; u += 256) {
            int chunk = u & 7;
            int px    = (u >> 3) % SPX;
            int rp    = (u >> 3) / SPX;
            int plane = rp & 1, r = rp >> 1;
            int hr = h - 1 + r, gpx = px - 1;
            uint32_t doff = rp * BPL + px * 128 + ((chunk ^ (px & 7)) << 4);
            if ((unsigned)hr < (unsigned)HH && (unsigned)gpx < (unsigned)WW) {
                const bf16* src = (plane ? slo : shi)
                    + ((size_t)((b * HH + hr) * WW + gpx)) * 128 + ci0 + chunk * 8;
                cpa16(su + doff, src);
            } else {
                *reinterpret_cast<uint4*>(sm + doff) = make_uint4(0, 0, 0, 0);
            }
        }
        cpa_commit();
    };
    auto stage_B2 = [&](int ci0) {           // x row h, no halo, CIN=256 -> planes rp 0,1
        for (int u = tid; u < 2 * 128 * 8; u += 256) {
            int chunk = u & 7;
            int px    = (u >> 3) & 127;
            int plane = (u >> 3) >> 7;
            const bf16* src = (plane ? xlo : xhi)
                + ((size_t)((b * HH + h) * WW + px)) * 256 + ci0 + chunk * 8;
            cpa16(su + plane * BPL + px * 128 + ((chunk ^ (px & 7)) << 4), src);
        }
        cpa_commit();
    };

    auto compute = [&](uint32_t Ab, uint32_t bhB, uint32_t blB, int sp0) {
#pragma unroll
        for (int k = 0; k < 4; k++) {
            uint32_t ah[2][4], al[2][4];
#pragma unroll
            for (int mt = 0; mt < 2; mt++) {
                int row = mo + mt * 16 + (lane & 15);
                int ck  = k * 2 + (lane >> 4);
                uint32_t off = row * 128 + ((ck ^ (row & 7)) << 4);
                ldsm4(Ab + off, ah[mt]);
                ldsm4(Ab + 16384 + off, al[mt]);
            }
#pragma unroll
            for (int np = 0; np < 4; np++) {
                uint32_t bh[4], bl[4];
                int px = sp0 + np * 16 + (lane & 7) + ((lane >> 4) << 3);
                int ck = k * 2 + ((lane >> 3) & 1);
                uint32_t off = px * 128 + ((ck ^ (px & 7)) << 4);
                ldsm4(bhB + off, bh);
                ldsm4(blB + off, bl);
#pragma unroll
                for (int mt = 0; mt < 2; mt++)
#pragma unroll
                    for (int sb = 0; sb < 2; sb++) {
                        float* cc = acc[mt][np * 2 + sb];
                        mma16816(cc, ah[mt], bh[sb * 2], bh[sb * 2 + 1]);
                        mma16816(cc, ah[mt], bl[sb * 2], bl[sb * 2 + 1]);
                        mma16816(cc, al[mt], bh[sb * 2], bh[sb * 2 + 1]);
                    }
            }
        }
    };

    stage_A(0, 0);
    // phase 1: c1 over s
    for (int c = 0; c < 2; c++) {
        stage_B1(c * 64);
        cpa_wait0();
        __syncthreads();
#pragma unroll 1
        for (int t = 0; t < 9; t++) {
            const int seq = c * 9 + t;
            stage_A(seq + 1, (seq + 1) & 1);
            const int r = t / 3, s = t % 3;
            compute(su + ABASE + (seq & 1) * ABUF,
                    su + (r * 2 + 0) * BPL, su + (r * 2 + 1) * BPL,
                    warpN * 64 + s);
            cpa_wait0();
            __syncthreads();
        }
    }
    // phase 2: c2 over x
    for (int c = 0; c < 4; c++) {
        stage_B2(c * 64);
        cpa_wait0();
        __syncthreads();
        const int seq = 18 + c;
        if (seq + 1 < 22) stage_A(seq + 1, (seq + 1) & 1);
        compute(su + ABASE + (seq & 1) * ABUF, su, su + BPL, warpN * 64);
        cpa_wait0();
        __syncthreads();
    }

    const int g = lane >> 2, q = lane & 3;
#pragma unroll
    for (int mt = 0; mt < 2; mt++)
#pragma unroll
        for (int half = 0; half < 2; half++) {
            const int co = co0 + mo + mt * 16 + g + half * 8;
            const float bi = b1[co] + b2[co];
            const size_t rowb = ((size_t)(b * COUT + co) * HH + h) * WW;
#pragma unroll
            for (int nt = 0; nt < 8; nt++) {
                const int px = warpN * 64 + nt * 8 + q * 2;
                float v0 = fmaxf(acc[mt][nt][half * 2 + 0] + bi, 0.f);
                float v1 = fmaxf(acc[mt][nt][half * 2 + 1] + bi, 0.f);
                *reinterpret_cast<float2*>(out + rowb + px) = make_float2(v0, v1);
            }
        }
}

// ------------------------- scans (exact, f32 NCHW) -------------------------
__global__ void colscan_kernel(float* __restrict__ p)
{
    int idx = blockIdx.x * blockDim.x + threadIdx.x;
    if (idx >= B_ * MID * WW) return;
    int w = idx % WW, bc = idx / WW;
    float* col = p + (size_t)bc * HW + w;
    float m = col[(HH - 1) * WW];
#pragma unroll 4
    for (int h = HH - 2; h >= 0; h--) {
        m = fmaxf(m, col[h * WW]);
        col[h * WW] = m;
    }
}
__global__ void rowscan_add_kernel(const float* __restrict__ p2, float* __restrict__ s)
{
    __shared__ float sm[WW];
    const int t = threadIdx.x;
    const size_t base = (size_t)blockIdx.x * WW;
    sm[t] = p2[base + t];
    __syncthreads();
#pragma unroll
    for (int off = 1; off < WW; off <<= 1) {
        float nv = sm[t];
        if (t + off < WW) nv = fmaxf(nv, sm[t + off]);
        __syncthreads();
        sm[t] = nv;
        __syncthreads();
    }
    s[base + t] += sm[t];
}

// ------------------------- launch -------------------------
extern "C" void kernel_launch(void* const* d_in, const int* in_sizes, int n_in,
                              void* d_out, int out_size)
{
    (void)in_sizes; (void)n_in; (void)out_size;

    const float* x = (const float*)d_in[0];

    float *p1, *p2, *t1, *sc, *bi;
    bf16 *xh, *xl, *sh, *sl, *rh, *rl, *wh, *wl;
    cudaGetSymbolAddress((void**)&p1, g_p1);
    cudaGetSymbolAddress((void**)&p2, g_p2);
    cudaGetSymbolAddress((void**)&t1, g_t1);
    cudaGetSymbolAddress((void**)&sc, g_scale);
    cudaGetSymbolAddress((void**)&bi, g_bias);
    cudaGetSymbolAddress((void**)&xh, g_xT_hi);
    cudaGetSymbolAddress((void**)&xl, g_xT_lo);
    cudaGetSymbolAddress((void**)&sh, g_sT_hi);
    cudaGetSymbolAddress((void**)&sl, g_sT_lo);
    cudaGetSymbolAddress((void**)&rh, g_rT_hi);
    cudaGetSymbolAddress((void**)&rl, g_rT_lo);
    cudaGetSymbolAddress((void**)&wh, g_w_hi);
    cudaGetSymbolAddress((void**)&wl, g_w_lo);

    constexpr int SM3 = 6 * 130 * 128 + 2 * 32768;   // 165376
    cudaFuncSetAttribute(conv3<true>,  cudaFuncAttributeMaxDynamicSharedMemorySize, SM3);
    cudaFuncSetAttribute(conv3<false>, cudaFuncAttributeMaxDynamicSharedMemorySize, SM3);
    cudaFuncSetAttribute(conv_c1c2,    cudaFuncAttributeMaxDynamicSharedMemorySize, SM3);

    // BN folding (scale+bias)
    bn_prep<<<1, 256>>>((const float*)d_in[2],  (const float*)d_in[3],  (const float*)d_in[4],  (const float*)d_in[5],  sc + 0,   bi + 0,   MID);
    bn_prep<<<1, 256>>>((const float*)d_in[7],  (const float*)d_in[8],  (const float*)d_in[9],  (const float*)d_in[10], sc + 128, bi + 128, MID);
    bn_prep<<<1, 256>>>((const float*)d_in[12], (const float*)d_in[13], (const float*)d_in[14], (const float*)d_in[15], sc + 256, bi + 256, DIM);
    bn_prep<<<1, 256>>>((const float*)d_in[17], (const float*)d_in[18], (const float*)d_in[19], (const float*)d_in[20], sc + 512, bi + 512, DIM);
    bn_prep<<<1, 256>>>((const float*)d_in[22], (const float*)d_in[23], (const float*)d_in[24], (const float*)d_in[25], sc + 768, bi + 768, DIM);

    // scale-folded, tap-sliced hi/lo weight split
    wsplit<<<MID * DIM / 256, 256>>>((const float*)d_in[1],  sc + 0,   wh + WOFF_P1, wl + WOFF_P1, MID, DIM, 9);
    wsplit<<<MID * DIM / 256, 256>>>((const float*)d_in[6],  sc + 128, wh + WOFF_P2, wl + WOFF_P2, MID, DIM, 9);
    wsplit<<<DIM * MID / 256, 256>>>((const float*)d_in[11], sc + 256, wh + WOFF_C1, wl + WOFF_C1, DIM, MID, 9);
    wsplit<<<DIM * DIM / 256, 256>>>((const float*)d_in[16], sc + 512, wh + WOFF_C2, wl + WOFF_C2, DIM, DIM, 1);
    wsplit<<<DIM * DIM / 256, 256>>>((const float*)d_in[21], sc + 768, wh + WOFF_P3, wl + WOFF_P3, DIM, DIM, 9);

    // x -> NHWC bf16 hi/lo
    split_T<<<dim3(HW / 32, DIM / 32, B_), 256>>>(x, xh, xl, DIM);

    // p1 + p2 in one launch (grid.y selects branch)
    conv3<true><<<dim3(B_ * HH, 2), 256, SM3>>>(
        xh, xl,
        wh + WOFF_P1, wl + WOFF_P1, wh + WOFF_P2, wl + WOFF_P2,
        bi + 0, bi + 128, p1, p2, MID);

    // corner pooling: p1 <- revcummax_H(p1) + revcummax_W(p2)
    colscan_kernel<<<(B_ * MID * WW + 255) / 256, 256>>>(p1);
    rowscan_add_kernel<<<B_ * MID * HH, WW>>>(p2, p1);

    // s -> NHWC hi/lo
    split_T<<<dim3(HW / 32, MID / 32, B_), 256>>>(p1, sh, sl, MID);

    // fused c1 + c2 -> r (in t1)
    conv_c1c2<<<dim3(B_ * HH, 2), 256, SM3>>>(
        sh, sl, xh, xl,
        wh + WOFF_C1, wl + WOFF_C1, wh + WOFF_C2, wl + WOFF_C2,
        bi + 256, bi + 512, t1);

    // r -> NHWC hi/lo; p3
    split_T<<<dim3(HW / 32, DIM / 32, B_), 256>>>(t1, rh, rl, DIM);
    conv3<false><<<dim3(B_ * HH, 2), 256, SM3>>>(
        rh, rl,
        wh + WOFF_P3, wl + WOFF_P3, nullptr, nullptr,
        bi + 768, nullptr, (float*)d_out, nullptr, DIM);
}

// round 13
// speedup vs baseline: 5.9600x; 1.3584x over previous
#include <cuda_runtime.h>
#include <cuda_fp16.h>
#include <cstdint>
#include <cstddef>

using h16 = __half;

constexpr int B_  = 4;
constexpr int DIM = 256;
constexpr int MID = 128;
constexpr int HH  = 128;
constexpr int WW  = 128;
constexpr int HW  = HH * WW;

// ------------------------- device scratch -------------------------
__device__ float g_p1[(size_t)B_ * MID * HW];
__device__ float g_p2[(size_t)B_ * MID * HW];
__device__ float g_t1[(size_t)B_ * DIM * HW];      // r
__device__ float g_scale[1024];
__device__ float g_bias[1024];

__device__ h16 g_xT_hi[(size_t)B_ * HW * DIM];
__device__ h16 g_xT_lo[(size_t)B_ * HW * DIM];
__device__ h16 g_sT_hi[(size_t)B_ * HW * MID];
__device__ h16 g_sT_lo[(size_t)B_ * HW * MID];
__device__ h16 g_rT_hi[(size_t)B_ * HW * DIM];
__device__ h16 g_rT_lo[(size_t)B_ * HW * DIM];

constexpr size_t WOFF_P1 = 0;
constexpr size_t WOFF_P2 = WOFF_P1 + (size_t)MID * DIM * 9;
constexpr size_t WOFF_C1 = WOFF_P2 + (size_t)MID * DIM * 9;
constexpr size_t WOFF_C2 = WOFF_C1 + (size_t)DIM * MID * 9;
constexpr size_t WOFF_P3 = WOFF_C2 + (size_t)DIM * DIM * 1;
constexpr size_t WTOT    = WOFF_P3 + (size_t)DIM * DIM * 9;
__device__ h16 g_w[WTOT];          // fp16, BN-scale folded

// ------------------------- helpers (sm_80+ generic) -------------------------
__device__ __forceinline__ uint32_t smem_u32(const void* p) {
    uint32_t a;
    asm("{ .reg .u64 t; cvta.to.shared.u64 t, %1; cvt.u32.u64 %0, t; }" : "=r"(a) : "l"(p));
    return a;
}
__device__ __forceinline__ void ldsm4(uint32_t addr, uint32_t* r) {
    asm volatile("ldmatrix.sync.aligned.m8n8.x4.shared.b16 {%0,%1,%2,%3}, [%4];"
                 : "=r"(r[0]), "=r"(r[1]), "=r"(r[2]), "=r"(r[3]) : "r"(addr));
}
__device__ __forceinline__ void mma16816(float* c, const uint32_t* a, uint32_t b0, uint32_t b1) {
    asm volatile("mma.sync.aligned.m16n8k16.row.col.f32.f16.f16.f32 "
                 "{%0,%1,%2,%3}, {%4,%5,%6,%7}, {%8,%9}, {%0,%1,%2,%3};"
                 : "+f"(c[0]), "+f"(c[1]), "+f"(c[2]), "+f"(c[3])
                 : "r"(a[0]), "r"(a[1]), "r"(a[2]), "r"(a[3]), "r"(b0), "r"(b1));
}
__device__ __forceinline__ void cpa16(uint32_t dst, const void* src) {
    asm volatile("cp.async.cg.shared.global [%0], [%1], 16;" :: "r"(dst), "l"(src) : "memory");
}
__device__ __forceinline__ void cpa_commit() { asm volatile("cp.async.commit_group;" ::: "memory"); }
__device__ __forceinline__ void cpa_wait0()  { asm volatile("cp.async.wait_group 0;" ::: "memory"); }

// ------------------------- prep kernels -------------------------
__global__ void bn_prep(const float* __restrict__ g, const float* __restrict__ b,
                        const float* __restrict__ m, const float* __restrict__ v,
                        float* __restrict__ scale, float* __restrict__ bias, int C)
{
    int i = blockIdx.x * blockDim.x + threadIdx.x;
    if (i < C) {
        float s = g[i] * rsqrtf(v[i] + 1e-5f);
        scale[i] = s;
        bias[i]  = b[i] - m[i] * s;
    }
}

// weights [co][ci][T] f32, BN-scale folded -> [tap][co][ci] fp16
__global__ void wsplit(const float* __restrict__ w, const float* __restrict__ scale,
                       h16* __restrict__ wo, int COUT, int CIN, int T)
{
    int i = blockIdx.x * 256 + threadIdx.x;
    if (i >= COUT * CIN) return;
    int co = i / CIN, ci = i % CIN;
    float sc = scale[co];
    for (int t = 0; t < T; t++) {
        float v = w[(size_t)i * T + t] * sc;
        wo[((size_t)t * COUT + co) * CIN + ci] = __float2half(v);
    }
}

// NCHW f32 -> NHWC fp16 hi/lo. grid (HW/32, C/32, B), block 256
__global__ void split_T(const float* __restrict__ in, h16* __restrict__ hi,
                        h16* __restrict__ lo, int C)
{
    __shared__ float t[32][33];
    int pt = blockIdx.x * 32, ct = blockIdx.y * 32, z = blockIdx.z;
    int tx = threadIdx.x & 31, ty = threadIdx.x >> 5;
#pragma unroll
    for (int j = 0; j < 32; j += 8)
        t[ty + j][tx] = in[((size_t)z * C + ct + ty + j) * HW + pt + tx];
    __syncthreads();
#pragma unroll
    for (int j = 0; j < 32; j += 8) {
        float v = t[tx][ty + j];
        h16 h = __float2half(v);
        size_t o = ((size_t)z * HW + pt + ty + j) * C + ct + tx;
        hi[o] = h;
        lo[o] = __float2half(v - __half2float(h));
    }
}

// ===================== generic 3x3 conv, CIN=256 ==========================
// CTA: 128 couts x 128 pixels (one image row). 8 warps: 4(M) x 2(N),
// warp tile 32co x 64px. fp16 2-term: acc += w*(x_hi) + w*(x_lo).
// DUAL: blockIdx.y selects {w,out,bias} set (p1/p2 batched). else y = co-tile.
template<bool DUAL>
__global__ __launch_bounds__(256, 1)
void conv3(const h16* __restrict__ xhi, const h16* __restrict__ xlo,
           const h16* __restrict__ w0, const h16* __restrict__ w1,
           const float* __restrict__ bias0, const float* __restrict__ bias1,
           float* __restrict__ out0, float* __restrict__ out1, int COUT)
{
    constexpr int CIN = 256;
    constexpr int SPX = 130, BPL = SPX * 128;
    constexpr int ABASE = 6 * BPL;
    constexpr int ABUF  = 16384;           // single plane: 128co x 64ci x 2B

    extern __shared__ char sm[];
    const uint32_t su = smem_u32(sm);

    const int tid = threadIdx.x, wid = tid >> 5, lane = tid & 31;
    const int h  = blockIdx.x & 127, b = blockIdx.x >> 7;
    const int y  = blockIdx.y;
    const int co0 = DUAL ? 0 : (y << 7);
    const h16* wgt = (DUAL && y) ? w1 : w0;
    const float* bias = (DUAL && y) ? bias1 : bias0;
    float* out = (DUAL && y) ? out1 : out0;

    const int warpM = wid >> 1, warpN = wid & 1;
    const int mo = warpM * 32;

    float acc[2][8][4];
#pragma unroll
    for (int i = 0; i < 2; i++)
#pragma unroll
        for (int j = 0; j < 8; j++)
#pragma unroll
            for (int k = 0; k < 4; k++) acc[i][j][k] = 0.f;

    auto stage_A = [&](int tap, int ci0, int buf) {
#pragma unroll
        for (int it = 0; it < 4; it++) {
            int u = tid + it * 256;
            int chunk = u & 7, co = u >> 3;
            const h16* src = wgt + ((size_t)(tap * COUT + co0 + co)) * CIN + ci0 + chunk * 8;
            cpa16(su + ABASE + buf * ABUF + co * 128 + ((chunk ^ (co & 7)) << 4), src);
        }
        cpa_commit();
    };
    auto stage_B = [&](int ci0) {
        for (int u = tid; u < 6 * SPX * 8; u += 256) {
            int chunk = u & 7;
            int px    = (u >> 3) % SPX;
            int rp    = (u >> 3) / SPX;
            int plane = rp & 1, r = rp >> 1;
            int hr = h - 1 + r, gpx = px - 1;
            uint32_t doff = rp * BPL + px * 128 + ((chunk ^ (px & 7)) << 4);
            if ((unsigned)hr < (unsigned)HH && (unsigned)gpx < (unsigned)WW) {
                const h16* src = (plane ? xlo : xhi)
                    + ((size_t)((b * HH + hr) * WW + gpx)) * CIN + ci0 + chunk * 8;
                cpa16(su + doff, src);
            } else {
                *reinterpret_cast<uint4*>(sm + doff) = make_uint4(0, 0, 0, 0);
            }
        }
        cpa_commit();
    };

    stage_A(0, 0, 0);
    for (int c = 0; c < 4; c++) {
        stage_B(c * 64);
        cpa_wait0();
        __syncthreads();
#pragma unroll 1
        for (int t = 0; t < 9; t++) {
            const int seq = c * 9 + t, nxt = seq + 1;
            if (nxt < 36) stage_A(nxt % 9, (nxt / 9) * 64, nxt & 1);

            const uint32_t Ab  = su + ABASE + (seq & 1) * ABUF;
            const int r = t / 3, s = t % 3;
            const uint32_t bhB = su + (r * 2 + 0) * BPL;
            const uint32_t blB = su + (r * 2 + 1) * BPL;
            const int sp0 = warpN * 64 + s;

#pragma unroll
            for (int k = 0; k < 4; k++) {
                uint32_t ah[2][4];
#pragma unroll
                for (int mt = 0; mt < 2; mt++) {
                    int row = mo + mt * 16 + (lane & 15);
                    int ck  = k * 2 + (lane >> 4);
                    ldsm4(Ab + row * 128 + ((ck ^ (row & 7)) << 4), ah[mt]);
                }
#pragma unroll
                for (int np = 0; np < 4; np++) {
                    uint32_t bh[4], bl[4];
                    int px = sp0 + np * 16 + (lane & 7) + ((lane >> 4) << 3);
                    int ck = k * 2 + ((lane >> 3) & 1);
                    uint32_t off = px * 128 + ((ck ^ (px & 7)) << 4);
                    ldsm4(bhB + off, bh);
                    ldsm4(blB + off, bl);
#pragma unroll
                    for (int mt = 0; mt < 2; mt++)
#pragma unroll
                        for (int sb = 0; sb < 2; sb++) {
                            float* cc = acc[mt][np * 2 + sb];
                            mma16816(cc, ah[mt], bh[sb * 2], bh[sb * 2 + 1]);
                            mma16816(cc, ah[mt], bl[sb * 2], bl[sb * 2 + 1]);
                        }
                }
            }
            cpa_wait0();
            __syncthreads();
        }
    }

    const int g = lane >> 2, q = lane & 3;
#pragma unroll
    for (int mt = 0; mt < 2; mt++)
#pragma unroll
        for (int half = 0; half < 2; half++) {
            const int co = co0 + mo + mt * 16 + g + half * 8;
            const float bi = bias[co];
            const size_t rowb = ((size_t)(b * COUT + co) * HH + h) * WW;
#pragma unroll
            for (int nt = 0; nt < 8; nt++) {
                const int px = warpN * 64 + nt * 8 + q * 2;
                float v0 = fmaxf(acc[mt][nt][half * 2 + 0] + bi, 0.f);
                float v1 = fmaxf(acc[mt][nt][half * 2 + 1] + bi, 0.f);
                *reinterpret_cast<float2*>(out + rowb + px) = make_float2(v0, v1);
            }
        }
}

// ===================== fused c1(3x3 over s) + c2(1x1 over x) ==============
__global__ __launch_bounds__(256, 1)
void conv_c1c2(const h16* __restrict__ shi, const h16* __restrict__ slo,
               const h16* __restrict__ xhi, const h16* __restrict__ xlo,
               const h16* __restrict__ w1, const h16* __restrict__ w2,
               const float* __restrict__ b1, const float* __restrict__ b2,
               float* __restrict__ out)
{
    constexpr int COUT = 256;
    constexpr int SPX = 130, BPL = SPX * 128;
    constexpr int ABASE = 6 * BPL;
    constexpr int ABUF  = 16384;

    extern __shared__ char sm[];
    const uint32_t su = smem_u32(sm);

    const int tid = threadIdx.x, wid = tid >> 5, lane = tid & 31;
    const int h  = blockIdx.x & 127, b = blockIdx.x >> 7;
    const int co0 = blockIdx.y << 7;
    const int warpM = wid >> 1, warpN = wid & 1;
    const int mo = warpM * 32;

    float acc[2][8][4];
#pragma unroll
    for (int i = 0; i < 2; i++)
#pragma unroll
        for (int j = 0; j < 8; j++)
#pragma unroll
            for (int k = 0; k < 4; k++) acc[i][j][k] = 0.f;

    // seq 0..17: c1 (tap=seq%9, chunk=seq/9, CIN=128); seq 18..21: c2 (chunk=seq-18, CIN=256)
    auto stage_A = [&](int seq, int buf) {
#pragma unroll
        for (int it = 0; it < 4; it++) {
            int u = tid + it * 256;
            int chunk = u & 7, co = u >> 3;
            const h16* src;
            if (seq < 18) {
                int tap = seq % 9, ch = seq / 9;
                src = w1 + ((size_t)(tap * COUT + co0 + co)) * 128 + ch * 64 + chunk * 8;
            } else {
                int ch = seq - 18;
                src = w2 + ((size_t)(co0 + co)) * 256 + ch * 64 + chunk * 8;
            }
            cpa16(su + ABASE + buf * ABUF + co * 128 + ((chunk ^ (co & 7)) << 4), src);
        }
        cpa_commit();
    };
    auto stage_B1 = [&](int ci0) {
        for (int u = tid; u < 6 * SPX * 8; u += 256) {
            int chunk = u & 7;
            int px    = (u >> 3) % SPX;
            int rp    = (u >> 3) / SPX;
            int plane = rp & 1, r = rp >> 1;
            int hr = h - 1 + r, gpx = px - 1;
            uint32_t doff = rp * BPL + px * 128 + ((chunk ^ (px & 7)) << 4);
            if ((unsigned)hr < (unsigned)HH && (unsigned)gpx < (unsigned)WW) {
                const h16* src = (plane ? slo : shi)
                    + ((size_t)((b * HH + hr) * WW + gpx)) * 128 + ci0 + chunk * 8;
                cpa16(su + doff, src);
            } else {
                *reinterpret_cast<uint4*>(sm + doff) = make_uint4(0, 0, 0, 0);
            }
        }
        cpa_commit();
    };
    auto stage_B2 = [&](int ci0) {
        for (int u = tid; u < 2 * 128 * 8; u += 256) {
            int chunk = u & 7;
            int px    = (u >> 3) & 127;
            int plane = (u >> 3) >> 7;
            const h16* src = (plane ? xlo : xhi)
                + ((size_t)((b * HH + h) * WW + px)) * 256 + ci0 + chunk * 8;
            cpa16(su + plane * BPL + px * 128 + ((chunk ^ (px & 7)) << 4), src);
        }
        cpa_commit();
    };

    auto compute = [&](uint32_t Ab, uint32_t bhB, uint32_t blB, int sp0) {
#pragma unroll
        for (int k = 0; k < 4; k++) {
            uint32_t ah[2][4];
#pragma unroll
            for (int mt = 0; mt < 2; mt++) {
                int row = mo + mt * 16 + (lane & 15);
                int ck  = k * 2 + (lane >> 4);
                ldsm4(Ab + row * 128 + ((ck ^ (row & 7)) << 4), ah[mt]);
            }
#pragma unroll
            for (int np = 0; np < 4; np++) {
                uint32_t bh[4], bl[4];
                int px = sp0 + np * 16 + (lane & 7) + ((lane >> 4) << 3);
                int ck = k * 2 + ((lane >> 3) & 1);
                uint32_t off = px * 128 + ((ck ^ (px & 7)) << 4);
                ldsm4(bhB + off, bh);
                ldsm4(blB + off, bl);
#pragma unroll
                for (int mt = 0; mt < 2; mt++)
#pragma unroll
                    for (int sb = 0; sb < 2; sb++) {
                        float* cc = acc[mt][np * 2 + sb];
                        mma16816(cc, ah[mt], bh[sb * 2], bh[sb * 2 + 1]);
                        mma16816(cc, ah[mt], bl[sb * 2], bl[sb * 2 + 1]);
                    }
            }
        }
    };

    stage_A(0, 0);
    // phase 1: c1 over s (CIN=128, 2 chunks x 9 taps)
    for (int c = 0; c < 2; c++) {
        stage_B1(c * 64);
        cpa_wait0();
        __syncthreads();
#pragma unroll 1
        for (int t = 0; t < 9; t++) {
            const int seq = c * 9 + t;
            stage_A(seq + 1, (seq + 1) & 1);
            const int r = t / 3, s = t % 3;
            compute(su + ABASE + (seq & 1) * ABUF,
                    su + (r * 2 + 0) * BPL, su + (r * 2 + 1) * BPL,
                    warpN * 64 + s);
            cpa_wait0();
            __syncthreads();
        }
    }
    // phase 2: c2 over x (CIN=256, 4 chunks, 1x1)
    for (int c = 0; c < 4; c++) {
        stage_B2(c * 64);
        cpa_wait0();
        __syncthreads();
        const int seq = 18 + c;
        if (seq + 1 < 22) stage_A(seq + 1, (seq + 1) & 1);
        compute(su + ABASE + (seq & 1) * ABUF, su, su + BPL, warpN * 64);
        cpa_wait0();
        __syncthreads();
    }

    const int g = lane >> 2, q = lane & 3;
#pragma unroll
    for (int mt = 0; mt < 2; mt++)
#pragma unroll
        for (int half = 0; half < 2; half++) {
            const int co = co0 + mo + mt * 16 + g + half * 8;
            const float bi = b1[co] + b2[co];
            const size_t rowb = ((size_t)(b * COUT + co) * HH + h) * WW;
#pragma unroll
            for (int nt = 0; nt < 8; nt++) {
                const int px = warpN * 64 + nt * 8 + q * 2;
                float v0 = fmaxf(acc[mt][nt][half * 2 + 0] + bi, 0.f);
                float v1 = fmaxf(acc[mt][nt][half * 2 + 1] + bi, 0.f);
                *reinterpret_cast<float2*>(out + rowb + px) = make_float2(v0, v1);
            }
        }
}

// ------------------------- scans (exact, f32 NCHW) -------------------------
__global__ void colscan_kernel(float* __restrict__ p)
{
    int idx = blockIdx.x * blockDim.x + threadIdx.x;
    if (idx >= B_ * MID * WW) return;
    int w = idx % WW, bc = idx / WW;
    float* col = p + (size_t)bc * HW + w;
    float m = col[(HH - 1) * WW];
#pragma unroll 4
    for (int h = HH - 2; h >= 0; h--) {
        m = fmaxf(m, col[h * WW]);
        col[h * WW] = m;
    }
}
__global__ void rowscan_add_kernel(const float* __restrict__ p2, float* __restrict__ s)
{
    __shared__ float sm[WW];
    const int t = threadIdx.x;
    const size_t base = (size_t)blockIdx.x * WW;
    sm[t] = p2[base + t];
    __syncthreads();
#pragma unroll
    for (int off = 1; off < WW; off <<= 1) {
        float nv = sm[t];
        if (t + off < WW) nv = fmaxf(nv, sm[t + off]);
        __syncthreads();
        sm[t] = nv;
        __syncthreads();
    }
    s[base + t] += sm[t];
}

// ------------------------- launch -------------------------
extern "C" void kernel_launch(void* const* d_in, const int* in_sizes, int n_in,
                              void* d_out, int out_size)
{
    (void)in_sizes; (void)n_in; (void)out_size;

    const float* x = (const float*)d_in[0];

    float *p1, *p2, *t1, *sc, *bi;
    h16 *xh, *xl, *sh, *sl, *rh, *rl, *wp;
    cudaGetSymbolAddress((void**)&p1, g_p1);
    cudaGetSymbolAddress((void**)&p2, g_p2);
    cudaGetSymbolAddress((void**)&t1, g_t1);
    cudaGetSymbolAddress((void**)&sc, g_scale);
    cudaGetSymbolAddress((void**)&bi, g_bias);
    cudaGetSymbolAddress((void**)&xh, g_xT_hi);
    cudaGetSymbolAddress((void**)&xl, g_xT_lo);
    cudaGetSymbolAddress((void**)&sh, g_sT_hi);
    cudaGetSymbolAddress((void**)&sl, g_sT_lo);
    cudaGetSymbolAddress((void**)&rh, g_rT_hi);
    cudaGetSymbolAddress((void**)&rl, g_rT_lo);
    cudaGetSymbolAddress((void**)&wp, g_w);

    constexpr int SM3 = 6 * 130 * 128 + 2 * 16384;   // 132608
    cudaFuncSetAttribute(conv3<true>,  cudaFuncAttributeMaxDynamicSharedMemorySize, SM3);
    cudaFuncSetAttribute(conv3<false>, cudaFuncAttributeMaxDynamicSharedMemorySize, SM3);
    cudaFuncSetAttribute(conv_c1c2,    cudaFuncAttributeMaxDynamicSharedMemorySize, SM3);

    // BN folding (scale+bias)
    bn_prep<<<1, 256>>>((const float*)d_in[2],  (const float*)d_in[3],  (const float*)d_in[4],  (const float*)d_in[5],  sc + 0,   bi + 0,   MID);
    bn_prep<<<1, 256>>>((const float*)d_in[7],  (const float*)d_in[8],  (const float*)d_in[9],  (const float*)d_in[10], sc + 128, bi + 128, MID);
    bn_prep<<<1, 256>>>((const float*)d_in[12], (const float*)d_in[13], (const float*)d_in[14], (const float*)d_in[15], sc + 256, bi + 256, DIM);
    bn_prep<<<1, 256>>>((const float*)d_in[17], (const float*)d_in[18], (const float*)d_in[19], (const float*)d_in[20], sc + 512, bi + 512, DIM);
    bn_prep<<<1, 256>>>((const float*)d_in[22], (const float*)d_in[23], (const float*)d_in[24], (const float*)d_in[25], sc + 768, bi + 768, DIM);

    // scale-folded, tap-sliced fp16 weights
    wsplit<<<MID * DIM / 256, 256>>>((const float*)d_in[1],  sc + 0,   wp + WOFF_P1, MID, DIM, 9);
    wsplit<<<MID * DIM / 256, 256>>>((const float*)d_in[6],  sc + 128, wp + WOFF_P2, MID, DIM, 9);
    wsplit<<<DIM * MID / 256, 256>>>((const float*)d_in[11], sc + 256, wp + WOFF_C1, DIM, MID, 9);
    wsplit<<<DIM * DIM / 256, 256>>>((const float*)d_in[16], sc + 512, wp + WOFF_C2, DIM, DIM, 1);
    wsplit<<<DIM * DIM / 256, 256>>>((const float*)d_in[21], sc + 768, wp + WOFF_P3, DIM, DIM, 9);

    // x -> NHWC fp16 hi/lo
    split_T<<<dim3(HW / 32, DIM / 32, B_), 256>>>(x, xh, xl, DIM);

    // p1 + p2 in one launch (grid.y selects branch)
    conv3<true><<<dim3(B_ * HH, 2), 256, SM3>>>(
        xh, xl, wp + WOFF_P1, wp + WOFF_P2, bi + 0, bi + 128, p1, p2, MID);

    // corner pooling: p1 <- revcummax_H(p1) + revcummax_W(p2)
    colscan_kernel<<<(B_ * MID * WW + 255) / 256, 256>>>(p1);
    rowscan_add_kernel<<<B_ * MID * HH, WW>>>(p2, p1);

    // s -> NHWC fp16 hi/lo
    split_T<<<dim3(HW / 32, MID / 32, B_), 256>>>(p1, sh, sl, MID);

    // fused c1 + c2 -> r (in t1)
    conv_c1c2<<<dim3(B_ * HH, 2), 256, SM3>>>(
        sh, sl, xh, xl, wp + WOFF_C1, wp + WOFF_C2, bi + 256, bi + 512, t1);

    // r -> NHWC fp16 hi/lo; p3
    split_T<<<dim3(HW / 32, DIM / 32, B_), 256>>>(t1, rh, rl, DIM);
    conv3<false><<<dim3(B_ * HH, 2), 256, SM3>>>(
        rh, rl, wp + WOFF_P3, nullptr, bi + 768, nullptr, (float*)d_out, nullptr, DIM);
}

// round 14
// speedup vs baseline: 6.2790x; 1.0535x over previous
#include <cuda_runtime.h>
#include <cuda_fp16.h>
#include <cstdint>
#include <cstddef>

using h16 = __half;

constexpr int B_  = 4;
constexpr int DIM = 256;
constexpr int MID = 128;
constexpr int HH  = 128;
constexpr int WW  = 128;
constexpr int HW  = HH * WW;

// ------------------------- device scratch -------------------------
__device__ float g_p1[(size_t)B_ * MID * HW];
__device__ float g_p2[(size_t)B_ * MID * HW];
__device__ float g_t1[(size_t)B_ * DIM * HW];      // r
__device__ float g_scale[1024];
__device__ float g_bias[1024];

__device__ h16 g_xT_hi[(size_t)B_ * HW * DIM];
__device__ h16 g_xT_lo[(size_t)B_ * HW * DIM];
__device__ h16 g_sT_hi[(size_t)B_ * HW * MID];
__device__ h16 g_sT_lo[(size_t)B_ * HW * MID];
__device__ h16 g_rT_hi[(size_t)B_ * HW * DIM];
__device__ h16 g_rT_lo[(size_t)B_ * HW * DIM];

constexpr size_t WOFF_P1 = 0;
constexpr size_t WOFF_P2 = WOFF_P1 + (size_t)MID * DIM * 9;
constexpr size_t WOFF_C1 = WOFF_P2 + (size_t)MID * DIM * 9;
constexpr size_t WOFF_C2 = WOFF_C1 + (size_t)DIM * MID * 9;
constexpr size_t WOFF_P3 = WOFF_C2 + (size_t)DIM * DIM * 1;
constexpr size_t WTOT    = WOFF_P3 + (size_t)DIM * DIM * 9;
__device__ h16 g_w[WTOT];          // fp16, BN-scale folded

struct P5 { const float* p[5]; };

// ------------------------- helpers (sm_80+ generic) -------------------------
__device__ __forceinline__ uint32_t smem_u32(const void* p) {
    uint32_t a;
    asm("{ .reg .u64 t; cvta.to.shared.u64 t, %1; cvt.u32.u64 %0, t; }" : "=r"(a) : "l"(p));
    return a;
}
__device__ __forceinline__ void ldsm4(uint32_t addr, uint32_t* r) {
    asm volatile("ldmatrix.sync.aligned.m8n8.x4.shared.b16 {%0,%1,%2,%3}, [%4];"
                 : "=r"(r[0]), "=r"(r[1]), "=r"(r[2]), "=r"(r[3]) : "r"(addr));
}
__device__ __forceinline__ void mma16816(float* c, const uint32_t* a, uint32_t b0, uint32_t b1) {
    asm volatile("mma.sync.aligned.m16n8k16.row.col.f32.f16.f16.f32 "
                 "{%0,%1,%2,%3}, {%4,%5,%6,%7}, {%8,%9}, {%0,%1,%2,%3};"
                 : "+f"(c[0]), "+f"(c[1]), "+f"(c[2]), "+f"(c[3])
                 : "r"(a[0]), "r"(a[1]), "r"(a[2]), "r"(a[3]), "r"(b0), "r"(b1));
}
__device__ __forceinline__ void cpa16(uint32_t dst, const void* src) {
    asm volatile("cp.async.cg.shared.global [%0], [%1], 16;" :: "r"(dst), "l"(src) : "memory");
}
__device__ __forceinline__ void cpa_commit() { asm volatile("cp.async.commit_group;" ::: "memory"); }
__device__ __forceinline__ void cpa_wait0()  { asm volatile("cp.async.wait_group 0;" ::: "memory"); }

// ------------------------- merged prep kernels -------------------------
__global__ void bn_prep_all(P5 g, P5 b, P5 m, P5 v,
                            float* __restrict__ scale, float* __restrict__ bias)
{
    int i = blockIdx.x * 256 + threadIdx.x;     // 0..1023
    if (i >= 1024) return;
    int seg, off;
    if      (i < 128) { seg = 0; off = 0;   }
    else if (i < 256) { seg = 1; off = 128; }
    else if (i < 512) { seg = 2; off = 256; }
    else if (i < 768) { seg = 3; off = 512; }
    else              { seg = 4; off = 768; }
    int c = i - off;
    float s = g.p[seg][c] * rsqrtf(v.p[seg][c] + 1e-5f);
    scale[off + c] = s;
    bias[off + c]  = b.p[seg][c] - m.p[seg][c] * s;
}

__global__ void wsplit_all(P5 w, const float* __restrict__ scale, h16* __restrict__ wo)
{
    int i = blockIdx.x * 256 + threadIdx.x;     // 0..229375
    int seg, base, CIN, T, soff; size_t woff; int COUT;
    if      (i < 32768)  { seg = 0; base = 0;      COUT = 128; CIN = 256; T = 9; woff = WOFF_P1; soff = 0;   }
    else if (i < 65536)  { seg = 1; base = 32768;  COUT = 128; CIN = 256; T = 9; woff = WOFF_P2; soff = 128; }
    else if (i < 98304)  { seg = 2; base = 65536;  COUT = 256; CIN = 128; T = 9; woff = WOFF_C1; soff = 256; }
    else if (i < 163840) { seg = 3; base = 98304;  COUT = 256; CIN = 256; T = 1; woff = WOFF_C2; soff = 512; }
    else                 { seg = 4; base = 163840; COUT = 256; CIN = 256; T = 9; woff = WOFF_P3; soff = 768; }
    int j = i - base;
    int co = j / CIN, ci = j % CIN;
    float sc = scale[soff + co];
    const float* src = w.p[seg];
    for (int t = 0; t < T; t++)
        wo[woff + ((size_t)t * COUT + co) * CIN + ci] = __float2half(src[(size_t)j * T + t] * sc);
    (void)COUT;
}

// NCHW f32 -> NHWC fp16 hi/lo. grid (HW/32, C/32, B), block 256
__global__ void split_T(const float* __restrict__ in, h16* __restrict__ hi,
                        h16* __restrict__ lo, int C)
{
    __shared__ float t[32][33];
    int pt = blockIdx.x * 32, ct = blockIdx.y * 32, z = blockIdx.z;
    int tx = threadIdx.x & 31, ty = threadIdx.x >> 5;
#pragma unroll
    for (int j = 0; j < 32; j += 8)
        t[ty + j][tx] = in[((size_t)z * C + ct + ty + j) * HW + pt + tx];
    __syncthreads();
#pragma unroll
    for (int j = 0; j < 32; j += 8) {
        float v = t[tx][ty + j];
        h16 h = __float2half(v);
        size_t o = ((size_t)z * HW + pt + ty + j) * C + ct + tx;
        hi[o] = h;
        lo[o] = __float2half(v - __half2float(h));
    }
}

// ===================== generic 3x3 conv, CIN=256 ==========================
// CTA: 128 couts x 128 pixels. 8 warps: 4(M) x 2(N), warp tile 32co x 64px.
// B activations in a 4-slot row ring, prefetched 2 tap-groups ahead.
// fp16 2-term: acc += w*x_hi + w*x_lo.
template<bool DUAL>
__global__ __launch_bounds__(256, 1)
void conv3(const h16* __restrict__ xhi, const h16* __restrict__ xlo,
           const h16* __restrict__ w0, const h16* __restrict__ w1,
           const float* __restrict__ bias0, const float* __restrict__ bias1,
           float* __restrict__ out0, float* __restrict__ out1, int COUT)
{
    constexpr int CIN = 256;
    constexpr int SPX = 130, BPL = SPX * 128, SLOT = 2 * BPL;
    constexpr int ABASE = 4 * SLOT;            // 133120
    constexpr int ABUF  = 16384;
    constexpr int NG = 12;                     // 4 chunks x 3 rows

    extern __shared__ char sm[];
    const uint32_t su = smem_u32(sm);

    const int tid = threadIdx.x, wid = tid >> 5, lane = tid & 31;
    const int h  = blockIdx.x & 127, b = blockIdx.x >> 7;
    const int y  = blockIdx.y;
    const int co0 = DUAL ? 0 : (y << 7);
    const h16* wgt = (DUAL && y) ? w1 : w0;
    const float* bias = (DUAL && y) ? bias1 : bias0;
    float* out = (DUAL && y) ? out1 : out0;

    const int warpM = wid >> 1, warpN = wid & 1;
    const int mo = warpM * 32;

    float acc[2][8][4];
#pragma unroll
    for (int i = 0; i < 2; i++)
#pragma unroll
        for (int j = 0; j < 8; j++)
#pragma unroll
            for (int k = 0; k < 4; k++) acc[i][j][k] = 0.f;

    auto stage_A = [&](int tap, int ci0, int buf) {
#pragma unroll
        for (int it = 0; it < 4; it++) {
            int u = tid + it * 256;
            int chunk = u & 7, co = u >> 3;
            const h16* src = wgt + ((size_t)(tap * COUT + co0 + co)) * CIN + ci0 + chunk * 8;
            cpa16(su + ABASE + buf * ABUF + co * 128 + ((chunk ^ (co & 7)) << 4), src);
        }
        cpa_commit();
    };
    // stage one (plane) row of B: input row h-1+r, ci chunk c, into ring slot
    auto stage_Brow = [&](int plane, int c, int r, int slot) {
        const h16* basep = plane ? xlo : xhi;
        const int hr = h - 1 + r;
        for (int u = tid; u < SPX * 8; u += 256) {
            int chunk = u & 7, px = u >> 3;
            int gpx = px - 1;
            uint32_t doff = slot * SLOT + plane * BPL + px * 128 + ((chunk ^ (px & 7)) << 4);
            if ((unsigned)hr < (unsigned)HH && (unsigned)gpx < (unsigned)WW)
                cpa16(su + doff, basep + ((size_t)((b * HH + hr) * WW + gpx)) * CIN + c * 64 + chunk * 8);
            else
                *reinterpret_cast<uint4*>(sm + doff) = make_uint4(0, 0, 0, 0);
        }
        cpa_commit();
    };

    stage_Brow(0, 0, 0, 0); stage_Brow(1, 0, 0, 0);
    stage_Brow(0, 0, 1, 1); stage_Brow(1, 0, 1, 1);
    stage_A(0, 0, 0);
    cpa_wait0(); __syncthreads();

    int seq = 0;
    for (int gq = 0; gq < NG; gq++) {
        const int slot = gq & 3;
        const uint32_t bhB = su + slot * SLOT, blB = bhB + BPL;
        const int ng = gq + 2;
#pragma unroll 1
        for (int sl = 0; sl < 3; sl++, seq++) {
            const int nxt = seq + 1;
            if (nxt < 36) stage_A(nxt % 9, (nxt / 9) * 64, nxt & 1);
            if (ng < NG && sl < 2) stage_Brow(sl, ng / 3, ng % 3, ng & 3);

            const uint32_t Ab = su + ABASE + (seq & 1) * ABUF;
            const int sp0 = warpN * 64 + sl;
#pragma unroll
            for (int k = 0; k < 4; k++) {
                uint32_t ah[2][4];
#pragma unroll
                for (int mt = 0; mt < 2; mt++) {
                    int row = mo + mt * 16 + (lane & 15);
                    int ck  = k * 2 + (lane >> 4);
                    ldsm4(Ab + row * 128 + ((ck ^ (row & 7)) << 4), ah[mt]);
                }
#pragma unroll
                for (int np = 0; np < 4; np++) {
                    uint32_t bh[4], bl[4];
                    int px = sp0 + np * 16 + (lane & 7) + ((lane >> 4) << 3);
                    int ck = k * 2 + ((lane >> 3) & 1);
                    uint32_t off = px * 128 + ((ck ^ (px & 7)) << 4);
                    ldsm4(bhB + off, bh);
                    ldsm4(blB + off, bl);
#pragma unroll
                    for (int mt = 0; mt < 2; mt++)
#pragma unroll
                        for (int sb = 0; sb < 2; sb++) {
                            float* cc = acc[mt][np * 2 + sb];
                            mma16816(cc, ah[mt], bh[sb * 2], bh[sb * 2 + 1]);
                            mma16816(cc, ah[mt], bl[sb * 2], bl[sb * 2 + 1]);
                        }
                }
            }
            cpa_wait0(); __syncthreads();
        }
    }

    const int g = lane >> 2, q = lane & 3;
#pragma unroll
    for (int mt = 0; mt < 2; mt++)
#pragma unroll
        for (int half = 0; half < 2; half++) {
            const int co = co0 + mo + mt * 16 + g + half * 8;
            const float bi = bias[co];
            const size_t rowb = ((size_t)(b * COUT + co) * HH + h) * WW;
#pragma unroll
            for (int nt = 0; nt < 8; nt++) {
                const int px = warpN * 64 + nt * 8 + q * 2;
                float v0 = fmaxf(acc[mt][nt][half * 2 + 0] + bi, 0.f);
                float v1 = fmaxf(acc[mt][nt][half * 2 + 1] + bi, 0.f);
                *reinterpret_cast<float2*>(out + rowb + px) = make_float2(v0, v1);
            }
        }
}

// ===================== fused c1(3x3 over s) + c2(1x1 over x) ==============
__global__ __launch_bounds__(256, 1)
void conv_c1c2(const h16* __restrict__ shi, const h16* __restrict__ slo,
               const h16* __restrict__ xhi, const h16* __restrict__ xlo,
               const h16* __restrict__ w1, const h16* __restrict__ w2,
               const float* __restrict__ b1, const float* __restrict__ b2,
               float* __restrict__ out)
{
    constexpr int COUT = 256;
    constexpr int SPX = 130, BPL = SPX * 128, SLOT = 2 * BPL;
    constexpr int ABASE = 4 * SLOT;
    constexpr int ABUF  = 16384;
    constexpr int NG1 = 6;                     // phase1: 2 chunks x 3 rows

    extern __shared__ char sm[];
    const uint32_t su = smem_u32(sm);

    const int tid = threadIdx.x, wid = tid >> 5, lane = tid & 31;
    const int h  = blockIdx.x & 127, b = blockIdx.x >> 7;
    const int co0 = blockIdx.y << 7;
    const int warpM = wid >> 1, warpN = wid & 1;
    const int mo = warpM * 32;

    float acc[2][8][4];
#pragma unroll
    for (int i = 0; i < 2; i++)
#pragma unroll
        for (int j = 0; j < 8; j++)
#pragma unroll
            for (int k = 0; k < 4; k++) acc[i][j][k] = 0.f;

    // seq 0..17: c1 (tap=seq%9, chunk=seq/9, CIN=128); seq 18..21: c2 (chunk=seq-18, CIN=256)
    auto stage_A = [&](int seq, int buf) {
#pragma unroll
        for (int it = 0; it < 4; it++) {
            int u = tid + it * 256;
            int chunk = u & 7, co = u >> 3;
            const h16* src;
            if (seq < 18) {
                int tap = seq % 9, ch = seq / 9;
                src = w1 + ((size_t)(tap * COUT + co0 + co)) * 128 + ch * 64 + chunk * 8;
            } else {
                int ch = seq - 18;
                src = w2 + ((size_t)(co0 + co)) * 256 + ch * 64 + chunk * 8;
            }
            cpa16(su + ABASE + buf * ABUF + co * 128 + ((chunk ^ (co & 7)) << 4), src);
        }
        cpa_commit();
    };
    auto stage_Brow = [&](int plane, int c, int r, int slot) {   // s rows, CIN=128
        const h16* basep = plane ? slo : shi;
        const int hr = h - 1 + r;
        for (int u = tid; u < SPX * 8; u += 256) {
            int chunk = u & 7, px = u >> 3;
            int gpx = px - 1;
            uint32_t doff = slot * SLOT + plane * BPL + px * 128 + ((chunk ^ (px & 7)) << 4);
            if ((unsigned)hr < (unsigned)HH && (unsigned)gpx < (unsigned)WW)
                cpa16(su + doff, basep + ((size_t)((b * HH + hr) * WW + gpx)) * 128 + c * 64 + chunk * 8);
            else
                *reinterpret_cast<uint4*>(sm + doff) = make_uint4(0, 0, 0, 0);
        }
        cpa_commit();
    };
    auto stage_B2 = [&](int plane, int c, int slot) {            // x row h, CIN=256, no halo
        const h16* basep = plane ? xlo : xhi;
        for (int u = tid; u < 128 * 8; u += 256) {
            int chunk = u & 7, px = u >> 3;
            uint32_t doff = slot * SLOT + plane * BPL + px * 128 + ((chunk ^ (px & 7)) << 4);
            cpa16(su + doff, basep + ((size_t)((b * HH + h) * WW + px)) * 256 + c * 64 + chunk * 8);
        }
        cpa_commit();
    };

    auto compute = [&](uint32_t Ab, uint32_t bhB, uint32_t blB, int sp0) {
#pragma unroll
        for (int k = 0; k < 4; k++) {
            uint32_t ah[2][4];
#pragma unroll
            for (int mt = 0; mt < 2; mt++) {
                int row = mo + mt * 16 + (lane & 15);
                int ck  = k * 2 + (lane >> 4);
                ldsm4(Ab + row * 128 + ((ck ^ (row & 7)) << 4), ah[mt]);
            }
#pragma unroll
            for (int np = 0; np < 4; np++) {
                uint32_t bh[4], bl[4];
                int px = sp0 + np * 16 + (lane & 7) + ((lane >> 4) << 3);
                int ck = k * 2 + ((lane >> 3) & 1);
                uint32_t off = px * 128 + ((ck ^ (px & 7)) << 4);
                ldsm4(bhB + off, bh);
                ldsm4(blB + off, bl);
#pragma unroll
                for (int mt = 0; mt < 2; mt++)
#pragma unroll
                    for (int sb = 0; sb < 2; sb++) {
                        float* cc = acc[mt][np * 2 + sb];
                        mma16816(cc, ah[mt], bh[sb * 2], bh[sb * 2 + 1]);
                        mma16816(cc, ah[mt], bl[sb * 2], bl[sb * 2 + 1]);
                    }
            }
        }
    };

    stage_Brow(0, 0, 0, 0); stage_Brow(1, 0, 0, 0);
    stage_Brow(0, 0, 1, 1); stage_Brow(1, 0, 1, 1);
    stage_A(0, 0);
    cpa_wait0(); __syncthreads();

    int seq = 0;
    for (int gq = 0; gq < NG1; gq++) {
        const int slot = gq & 3;
        const uint32_t bhB = su + slot * SLOT, blB = bhB + BPL;
        const int ng = gq + 2;
#pragma unroll 1
        for (int sl = 0; sl < 3; sl++, seq++) {
            stage_A(seq + 1, (seq + 1) & 1);
            if (ng < NG1 && sl < 2) stage_Brow(sl, ng / 3, ng % 3, ng & 3);
            if (gq == NG1 - 1 && sl < 2) stage_B2(sl, 0, 2);     // prefetch c2 chunk0
            compute(su + ABASE + (seq & 1) * ABUF, bhB, blB, warpN * 64 + sl);
            cpa_wait0(); __syncthreads();
        }
    }
    // phase 2: c2 over x (4 chunks)
    for (int c2 = 0; c2 < 4; c2++) {
        const int slot = (c2 + 2) & 3;
        const int sq = 18 + c2;
        if (sq + 1 < 22) stage_A(sq + 1, (sq + 1) & 1);
        if (c2 + 1 < 4) { stage_B2(0, c2 + 1, (c2 + 3) & 3); stage_B2(1, c2 + 1, (c2 + 3) & 3); }
        compute(su + ABASE + (sq & 1) * ABUF, su + slot * SLOT, su + slot * SLOT + BPL, warpN * 64);
        cpa_wait0(); __syncthreads();
    }

    const int g = lane >> 2, q = lane & 3;
#pragma unroll
    for (int mt = 0; mt < 2; mt++)
#pragma unroll
        for (int half = 0; half < 2; half++) {
            const int co = co0 + mo + mt * 16 + g + half * 8;
            const float bi = b1[co] + b2[co];
            const size_t rowb = ((size_t)(b * COUT + co) * HH + h) * WW;
#pragma unroll
            for (int nt = 0; nt < 8; nt++) {
                const int px = warpN * 64 + nt * 8 + q * 2;
                float v0 = fmaxf(acc[mt][nt][half * 2 + 0] + bi, 0.f);
                float v1 = fmaxf(acc[mt][nt][half * 2 + 1] + bi, 0.f);
                *reinterpret_cast<float2*>(out + rowb + px) = make_float2(v0, v1);
            }
        }
}

// ------------------------- scans (exact, f32 NCHW) -------------------------
__global__ void colscan_kernel(float* __restrict__ p)
{
    int idx = blockIdx.x * blockDim.x + threadIdx.x;
    if (idx >= B_ * MID * WW) return;
    int w = idx % WW, bc = idx / WW;
    float* col = p + (size_t)bc * HW + w;
    float m = col[(HH - 1) * WW];
#pragma unroll 4
    for (int h = HH - 2; h >= 0; h--) {
        m = fmaxf(m, col[h * WW]);
        col[h * WW] = m;
    }
}
__global__ void rowscan_add_kernel(const float* __restrict__ p2, float* __restrict__ s)
{
    __shared__ float sm[WW];
    const int t = threadIdx.x;
    const size_t base = (size_t)blockIdx.x * WW;
    sm[t] = p2[base + t];
    __syncthreads();
#pragma unroll
    for (int off = 1; off < WW; off <<= 1) {
        float nv = sm[t];
        if (t + off < WW) nv = fmaxf(nv, sm[t + off]);
        __syncthreads();
        sm[t] = nv;
        __syncthreads();
    }
    s[base + t] += sm[t];
}

// ------------------------- launch -------------------------
extern "C" void kernel_launch(void* const* d_in, const int* in_sizes, int n_in,
                              void* d_out, int out_size)
{
    (void)in_sizes; (void)n_in; (void)out_size;

    const float* x = (const float*)d_in[0];

    float *p1, *p2, *t1, *sc, *bi;
    h16 *xh, *xl, *sh, *sl, *rh, *rl, *wp;
    cudaGetSymbolAddress((void**)&p1, g_p1);
    cudaGetSymbolAddress((void**)&p2, g_p2);
    cudaGetSymbolAddress((void**)&t1, g_t1);
    cudaGetSymbolAddress((void**)&sc, g_scale);
    cudaGetSymbolAddress((void**)&bi, g_bias);
    cudaGetSymbolAddress((void**)&xh, g_xT_hi);
    cudaGetSymbolAddress((void**)&xl, g_xT_lo);
    cudaGetSymbolAddress((void**)&sh, g_sT_hi);
    cudaGetSymbolAddress((void**)&sl, g_sT_lo);
    cudaGetSymbolAddress((void**)&rh, g_rT_hi);
    cudaGetSymbolAddress((void**)&rl, g_rT_lo);
    cudaGetSymbolAddress((void**)&wp, g_w);

    constexpr int SM3 = 4 * (2 * 130 * 128) + 2 * 16384;   // 165888
    cudaFuncSetAttribute(conv3<true>,  cudaFuncAttributeMaxDynamicSharedMemorySize, SM3);
    cudaFuncSetAttribute(conv3<false>, cudaFuncAttributeMaxDynamicSharedMemorySize, SM3);
    cudaFuncSetAttribute(conv_c1c2,    cudaFuncAttributeMaxDynamicSharedMemorySize, SM3);

    // merged BN folding + weight split
    P5 gg = {{(const float*)d_in[2],  (const float*)d_in[7],  (const float*)d_in[12], (const float*)d_in[17], (const float*)d_in[22]}};
    P5 bb = {{(const float*)d_in[3],  (const float*)d_in[8],  (const float*)d_in[13], (const float*)d_in[18], (const float*)d_in[23]}};
    P5 mm = {{(const float*)d_in[4],  (const float*)d_in[9],  (const float*)d_in[14], (const float*)d_in[19], (const float*)d_in[24]}};
    P5 vv = {{(const float*)d_in[5],  (const float*)d_in[10], (const float*)d_in[15], (const float*)d_in[20], (const float*)d_in[25]}};
    P5 ww = {{(const float*)d_in[1],  (const float*)d_in[6],  (const float*)d_in[11], (const float*)d_in[16], (const float*)d_in[21]}};
    bn_prep_all<<<4, 256>>>(gg, bb, mm, vv, sc, bi);
    wsplit_all<<<896, 256>>>(ww, sc, wp);

    // x -> NHWC fp16 hi/lo
    split_T<<<dim3(HW / 32, DIM / 32, B_), 256>>>(x, xh, xl, DIM);

    // p1 + p2 in one launch (grid.y selects branch)
    conv3<true><<<dim3(B_ * HH, 2), 256, SM3>>>(
        xh, xl, wp + WOFF_P1, wp + WOFF_P2, bi + 0, bi + 128, p1, p2, MID);

    // corner pooling: p1 <- revcummax_H(p1) + revcummax_W(p2)
    colscan_kernel<<<(B_ * MID * WW + 255) / 256, 256>>>(p1);
    rowscan_add_kernel<<<B_ * MID * HH, WW>>>(p2, p1);

    // s -> NHWC fp16 hi/lo
    split_T<<<dim3(HW / 32, MID / 32, B_), 256>>>(p1, sh, sl, MID);

    // fused c1 + c2 -> r (in t1)
    conv_c1c2<<<dim3(B_ * HH, 2), 256, SM3>>>(
        sh, sl, xh, xl, wp + WOFF_C1, wp + WOFF_C2, bi + 256, bi + 512, t1);

    // r -> NHWC fp16 hi/lo; p3
    split_T<<<dim3(HW / 32, DIM / 32, B_), 256>>>(t1, rh, rl, DIM);
    conv3<false><<<dim3(B_ * HH, 2), 256, SM3>>>(
        rh, rl, wp + WOFF_P3, nullptr, bi + 768, nullptr, (float*)d_out, nullptr, DIM);
}

// round 16
// speedup vs baseline: 6.4028x; 1.0197x over previous
#include <cuda_runtime.h>
#include <cuda_fp16.h>
#include <cstdint>
#include <cstddef>

using h16 = __half;

constexpr int B_  = 4;
constexpr int DIM = 256;
constexpr int MID = 128;
constexpr int HH  = 128;
constexpr int WW  = 128;
constexpr int HW  = HH * WW;

// ------------------------- device scratch -------------------------
__device__ float g_p1[(size_t)B_ * MID * HW];
__device__ float g_p2[(size_t)B_ * MID * HW];
__device__ float g_t1[(size_t)B_ * DIM * HW];      // r
__device__ float g_scale[1024];
__device__ float g_bias[1024];

__device__ h16 g_xT_hi[(size_t)B_ * HW * DIM];
__device__ h16 g_xT_lo[(size_t)B_ * HW * DIM];
__device__ h16 g_sT_hi[(size_t)B_ * HW * MID];
__device__ h16 g_sT_lo[(size_t)B_ * HW * MID];
__device__ h16 g_rT_hi[(size_t)B_ * HW * DIM];
__device__ h16 g_rT_lo[(size_t)B_ * HW * DIM];

constexpr size_t WOFF_P1 = 0;
constexpr size_t WOFF_P2 = WOFF_P1 + (size_t)MID * DIM * 9;
constexpr size_t WOFF_C1 = WOFF_P2 + (size_t)MID * DIM * 9;
constexpr size_t WOFF_C2 = WOFF_C1 + (size_t)DIM * MID * 9;
constexpr size_t WOFF_P3 = WOFF_C2 + (size_t)DIM * DIM * 1;
constexpr size_t WTOT    = WOFF_P3 + (size_t)DIM * DIM * 9;
__device__ h16 g_w[WTOT];          // fp16, BN-scale folded

struct P5 { const float* p[5]; };

// ------------------------- helpers (sm_80+ generic) -------------------------
__device__ __forceinline__ uint32_t smem_u32(const void* p) {
    uint32_t a;
    asm("{ .reg .u64 t; cvta.to.shared.u64 t, %1; cvt.u32.u64 %0, t; }" : "=r"(a) : "l"(p));
    return a;
}
__device__ __forceinline__ void ldsm4(uint32_t addr, uint32_t* r) {
    asm volatile("ldmatrix.sync.aligned.m8n8.x4.shared.b16 {%0,%1,%2,%3}, [%4];"
                 : "=r"(r[0]), "=r"(r[1]), "=r"(r[2]), "=r"(r[3]) : "r"(addr));
}
__device__ __forceinline__ void mma16816(float* c, const uint32_t* a, uint32_t b0, uint32_t b1) {
    asm volatile("mma.sync.aligned.m16n8k16.row.col.f32.f16.f16.f32 "
                 "{%0,%1,%2,%3}, {%4,%5,%6,%7}, {%8,%9}, {%0,%1,%2,%3};"
                 : "+f"(c[0]), "+f"(c[1]), "+f"(c[2]), "+f"(c[3])
                 : "r"(a[0]), "r"(a[1]), "r"(a[2]), "r"(a[3]), "r"(b0), "r"(b1));
}
__device__ __forceinline__ void cpa16(uint32_t dst, const void* src) {
    asm volatile("cp.async.cg.shared.global [%0], [%1], 16;" :: "r"(dst), "l"(src) : "memory");
}
__device__ __forceinline__ void cpa_commit() { asm volatile("cp.async.commit_group;" ::: "memory"); }
__device__ __forceinline__ void cpa_wait0()  { asm volatile("cp.async.wait_group 0;" ::: "memory"); }

// ------------------------- merged prep kernels -------------------------
__global__ void bn_prep_all(P5 g, P5 b, P5 m, P5 v,
                            float* __restrict__ scale, float* __restrict__ bias)
{
    int i = blockIdx.x * 256 + threadIdx.x;     // 0..1023
    if (i >= 1024) return;
    int seg, off;
    if      (i < 128) { seg = 0; off = 0;   }
    else if (i < 256) { seg = 1; off = 128; }
    else if (i < 512) { seg = 2; off = 256; }
    else if (i < 768) { seg = 3; off = 512; }
    else              { seg = 4; off = 768; }
    int c = i - off;
    float s = g.p[seg][c] * rsqrtf(v.p[seg][c] + 1e-5f);
    scale[off + c] = s;
    bias[off + c]  = b.p[seg][c] - m.p[seg][c] * s;
}

__global__ void wsplit_all(P5 w, const float* __restrict__ scale, h16* __restrict__ wo)
{
    int i = blockIdx.x * 256 + threadIdx.x;     // 0..229375
    int seg, base, CIN, T, soff; size_t woff; int COUT;
    if      (i < 32768)  { seg = 0; base = 0;      COUT = 128; CIN = 256; T = 9; woff = WOFF_P1; soff = 0;   }
    else if (i < 65536)  { seg = 1; base = 32768;  COUT = 128; CIN = 256; T = 9; woff = WOFF_P2; soff = 128; }
    else if (i < 98304)  { seg = 2; base = 65536;  COUT = 256; CIN = 128; T = 9; woff = WOFF_C1; soff = 256; }
    else if (i < 163840) { seg = 3; base = 98304;  COUT = 256; CIN = 256; T = 1; woff = WOFF_C2; soff = 512; }
    else                 { seg = 4; base = 163840; COUT = 256; CIN = 256; T = 9; woff = WOFF_P3; soff = 768; }
    int j = i - base;
    int co = j / CIN, ci = j % CIN;
    float sc = scale[soff + co];
    const float* src = w.p[seg];
    for (int t = 0; t < T; t++)
        wo[woff + ((size_t)t * COUT + co) * CIN + ci] = __float2half(src[(size_t)j * T + t] * sc);
    (void)COUT;
}

// NCHW f32 -> NHWC fp16 hi/lo. grid (HW/32, C/32, B), block 256
__global__ void split_T(const float* __restrict__ in, h16* __restrict__ hi,
                        h16* __restrict__ lo, int C)
{
    __shared__ float t[32][33];
    int pt = blockIdx.x * 32, ct = blockIdx.y * 32, z = blockIdx.z;
    int tx = threadIdx.x & 31, ty = threadIdx.x >> 5;
#pragma unroll
    for (int j = 0; j < 32; j += 8)
        t[ty + j][tx] = in[((size_t)z * C + ct + ty + j) * HW + pt + tx];
    __syncthreads();
#pragma unroll
    for (int j = 0; j < 32; j += 8) {
        float v = t[tx][ty + j];
        h16 h = __float2half(v);
        size_t o = ((size_t)z * HW + pt + ty + j) * C + ct + tx;
        hi[o] = h;
        lo[o] = __float2half(v - __half2float(h));
    }
}

// ===================== generic 3x3 conv, CIN=256, 64-px tile ===============
// CTA: 128 couts x 64 pixels (half row). 8 warps: 4(M) x 2(N), warp 32co x 32px.
// 2 CTAs/SM co-residency hides staging/sync bubbles. B in 4-slot row ring.
template<bool DUAL>
__global__ __launch_bounds__(256, 2)
void conv3(const h16* __restrict__ xhi, const h16* __restrict__ xlo,
           const h16* __restrict__ w0, const h16* __restrict__ w1,
           const float* __restrict__ bias0, const float* __restrict__ bias1,
           float* __restrict__ out0, float* __restrict__ out1, int COUT)
{
    constexpr int CIN = 256;
    constexpr int SPX = 66, BPL = SPX * 128, SLOT = 2 * BPL;   // 8448, 16896
    constexpr int ABASE = 4 * SLOT;                            // 67584
    constexpr int ABUF  = 16384;
    constexpr int NG = 12;

    extern __shared__ char sm[];
    const uint32_t su = smem_u32(sm);

    const int tid = threadIdx.x, wid = tid >> 5, lane = tid & 31;
    const int bx = blockIdx.x;
    const int half = bx & 1;
    const int h  = (bx >> 1) & 127, b = bx >> 8;
    const int w0p = half * 64;
    const int y  = blockIdx.y;
    const int co0 = DUAL ? 0 : (y << 7);
    const h16* wgt = (DUAL && y) ? w1 : w0;
    const float* bias = (DUAL && y) ? bias1 : bias0;
    float* out = (DUAL && y) ? out1 : out0;

    const int warpM = wid >> 1, warpN = wid & 1;
    const int mo = warpM * 32;

    float acc[2][4][4];
#pragma unroll
    for (int i = 0; i < 2; i++)
#pragma unroll
        for (int j = 0; j < 4; j++)
#pragma unroll
            for (int k = 0; k < 4; k++) acc[i][j][k] = 0.f;

    auto stage_A = [&](int tap, int ci0, int buf) {
#pragma unroll
        for (int it = 0; it < 4; it++) {
            int u = tid + it * 256;
            int chunk = u & 7, co = u >> 3;
            const h16* src = wgt + ((size_t)(tap * COUT + co0 + co)) * CIN + ci0 + chunk * 8;
            cpa16(su + ABASE + buf * ABUF + co * 128 + ((chunk ^ (co & 7)) << 4), src);
        }
        cpa_commit();
    };
    auto stage_Brow = [&](int plane, int c, int r, int slot) {
        const h16* basep = plane ? xlo : xhi;
        const int hr = h - 1 + r;
        for (int u = tid; u < SPX * 8; u += 256) {
            int chunk = u & 7, px = u >> 3;
            int gpx = w0p - 1 + px;
            uint32_t doff = slot * SLOT + plane * BPL + px * 128 + ((chunk ^ (px & 7)) << 4);
            if ((unsigned)hr < (unsigned)HH && (unsigned)gpx < (unsigned)WW)
                cpa16(su + doff, basep + ((size_t)((b * HH + hr) * WW + gpx)) * CIN + c * 64 + chunk * 8);
            else
                *reinterpret_cast<uint4*>(sm + doff) = make_uint4(0, 0, 0, 0);
        }
        cpa_commit();
    };

    stage_Brow(0, 0, 0, 0); stage_Brow(1, 0, 0, 0);
    stage_Brow(0, 0, 1, 1); stage_Brow(1, 0, 1, 1);
    stage_A(0, 0, 0);
    cpa_wait0(); __syncthreads();

    int seq = 0;
    for (int gq = 0; gq < NG; gq++) {
        const int slot = gq & 3;
        const uint32_t bhB = su + slot * SLOT, blB = bhB + BPL;
        const int ng = gq + 2;
#pragma unroll 1
        for (int sl = 0; sl < 3; sl++, seq++) {
            const int nxt = seq + 1;
            if (nxt < 36) stage_A(nxt % 9, (nxt / 9) * 64, nxt & 1);
            if (ng < NG && sl < 2) stage_Brow(sl, ng / 3, ng % 3, ng & 3);

            const uint32_t Ab = su + ABASE + (seq & 1) * ABUF;
            const int sp0 = warpN * 32 + sl;
#pragma unroll
            for (int k = 0; k < 4; k++) {
                uint32_t ah[2][4];
#pragma unroll
                for (int mt = 0; mt < 2; mt++) {
                    int row = mo + mt * 16 + (lane & 15);
                    int ck  = k * 2 + (lane >> 4);
                    ldsm4(Ab + row * 128 + ((ck ^ (row & 7)) << 4), ah[mt]);
                }
#pragma unroll
                for (int np = 0; np < 2; np++) {
                    uint32_t bh[4], bl[4];
                    int px = sp0 + np * 16 + (lane & 7) + ((lane >> 4) << 3);
                    int ck = k * 2 + ((lane >> 3) & 1);
                    uint32_t off = px * 128 + ((ck ^ (px & 7)) << 4);
                    ldsm4(bhB + off, bh);
                    ldsm4(blB + off, bl);
#pragma unroll
                    for (int mt = 0; mt < 2; mt++)
#pragma unroll
                        for (int sb = 0; sb < 2; sb++) {
                            float* cc = acc[mt][np * 2 + sb];
                            mma16816(cc, ah[mt], bh[sb * 2], bh[sb * 2 + 1]);
                            mma16816(cc, ah[mt], bl[sb * 2], bl[sb * 2 + 1]);
                        }
                }
            }
            cpa_wait0(); __syncthreads();
        }
    }

    const int g = lane >> 2, q = lane & 3;
#pragma unroll
    for (int mt = 0; mt < 2; mt++)
#pragma unroll
        for (int half2 = 0; half2 < 2; half2++) {
            const int co = co0 + mo + mt * 16 + g + half2 * 8;
            const float bi = bias[co];
            const size_t rowb = ((size_t)(b * COUT + co) * HH + h) * WW;
#pragma unroll
            for (int nt = 0; nt < 4; nt++) {
                const int px = w0p + warpN * 32 + nt * 8 + q * 2;
                float v0 = fmaxf(acc[mt][nt][half2 * 2 + 0] + bi, 0.f);
                float v1 = fmaxf(acc[mt][nt][half2 * 2 + 1] + bi, 0.f);
                *reinterpret_cast<float2*>(out + rowb + px) = make_float2(v0, v1);
            }
        }
}

// ===================== fused c1(3x3 over s) + c2(1x1 over x), 64-px ========
__global__ __launch_bounds__(256, 2)
void conv_c1c2(const h16* __restrict__ shi, const h16* __restrict__ slo,
               const h16* __restrict__ xhi, const h16* __restrict__ xlo,
               const h16* __restrict__ w1, const h16* __restrict__ w2,
               const float* __restrict__ b1, const float* __restrict__ b2,
               float* __restrict__ out)
{
    constexpr int COUT = 256;
    constexpr int SPX = 66, BPL = SPX * 128, SLOT = 2 * BPL;
    constexpr int ABASE = 4 * SLOT;
    constexpr int ABUF  = 16384;
    constexpr int NG1 = 6;

    extern __shared__ char sm[];
    const uint32_t su = smem_u32(sm);

    const int tid = threadIdx.x, wid = tid >> 5, lane = tid & 31;
    const int bx = blockIdx.x;
    const int half = bx & 1;
    const int h  = (bx >> 1) & 127, b = bx >> 8;
    const int w0p = half * 64;
    const int co0 = blockIdx.y << 7;
    const int warpM = wid >> 1, warpN = wid & 1;
    const int mo = warpM * 32;

    float acc[2][4][4];
#pragma unroll
    for (int i = 0; i < 2; i++)
#pragma unroll
        for (int j = 0; j < 4; j++)
#pragma unroll
            for (int k = 0; k < 4; k++) acc[i][j][k] = 0.f;

    auto stage_A = [&](int seq, int buf) {
#pragma unroll
        for (int it = 0; it < 4; it++) {
            int u = tid + it * 256;
            int chunk = u & 7, co = u >> 3;
            const h16* src;
            if (seq < 18) {
                int tap = seq % 9, ch = seq / 9;
                src = w1 + ((size_t)(tap * COUT + co0 + co)) * 128 + ch * 64 + chunk * 8;
            } else {
                int ch = seq - 18;
                src = w2 + ((size_t)(co0 + co)) * 256 + ch * 64 + chunk * 8;
            }
            cpa16(su + ABASE + buf * ABUF + co * 128 + ((chunk ^ (co & 7)) << 4), src);
        }
        cpa_commit();
    };
    auto stage_Brow = [&](int plane, int c, int r, int slot) {   // s rows, CIN=128
        const h16* basep = plane ? slo : shi;
        const int hr = h - 1 + r;
        for (int u = tid; u < SPX * 8; u += 256) {
            int chunk = u & 7, px = u >> 3;
            int gpx = w0p - 1 + px;
            uint32_t doff = slot * SLOT + plane * BPL + px * 128 + ((chunk ^ (px & 7)) << 4);
            if ((unsigned)hr < (unsigned)HH && (unsigned)gpx < (unsigned)WW)
                cpa16(su + doff, basep + ((size_t)((b * HH + hr) * WW + gpx)) * 128 + c * 64 + chunk * 8);
            else
                *reinterpret_cast<uint4*>(sm + doff) = make_uint4(0, 0, 0, 0);
        }
        cpa_commit();
    };
    auto stage_B2 = [&](int plane, int c, int slot) {            // x row h, 64px, CIN=256
        const h16* basep = plane ? xlo : xhi;
        for (int u = tid; u < 64 * 8; u += 256) {
            int chunk = u & 7, px = u >> 3;
            uint32_t doff = slot * SLOT + plane * BPL + px * 128 + ((chunk ^ (px & 7)) << 4);
            cpa16(su + doff, basep + ((size_t)((b * HH + h) * WW + w0p + px)) * 256 + c * 64 + chunk * 8);
        }
        cpa_commit();
    };

    auto compute = [&](uint32_t Ab, uint32_t bhB, uint32_t blB, int sp0) {
#pragma unroll
        for (int k = 0; k < 4; k++) {
            uint32_t ah[2][4];
#pragma unroll
            for (int mt = 0; mt < 2; mt++) {
                int row = mo + mt * 16 + (lane & 15);
                int ck  = k * 2 + (lane >> 4);
                ldsm4(Ab + row * 128 + ((ck ^ (row & 7)) << 4), ah[mt]);
            }
#pragma unroll
            for (int np = 0; np < 2; np++) {
                uint32_t bh[4], bl[4];
                int px = sp0 + np * 16 + (lane & 7) + ((lane >> 4) << 3);
                int ck = k * 2 + ((lane >> 3) & 1);
                uint32_t off = px * 128 + ((ck ^ (px & 7)) << 4);
                ldsm4(bhB + off, bh);
                ldsm4(blB + off, bl);
#pragma unroll
                for (int mt = 0; mt < 2; mt++)
#pragma unroll
                    for (int sb = 0; sb < 2; sb++) {
                        float* cc = acc[mt][np * 2 + sb];
                        mma16816(cc, ah[mt], bh[sb * 2], bh[sb * 2 + 1]);
                        mma16816(cc, ah[mt], bl[sb * 2], bl[sb * 2 + 1]);
                    }
            }
        }
    };

    stage_Brow(0, 0, 0, 0); stage_Brow(1, 0, 0, 0);
    stage_Brow(0, 0, 1, 1); stage_Brow(1, 0, 1, 1);
    stage_A(0, 0);
    cpa_wait0(); __syncthreads();

    int seq = 0;
    for (int gq = 0; gq < NG1; gq++) {
        const int slot = gq & 3;
        const uint32_t bhB = su + slot * SLOT, blB = bhB + BPL;
        const int ng = gq + 2;
#pragma unroll 1
        for (int sl = 0; sl < 3; sl++, seq++) {
            stage_A(seq + 1, (seq + 1) & 1);
            if (ng < NG1 && sl < 2) stage_Brow(sl, ng / 3, ng % 3, ng & 3);
            if (gq == NG1 - 1 && sl < 2) stage_B2(sl, 0, 2);     // prefetch c2 chunk0
            compute(su + ABASE + (seq & 1) * ABUF, bhB, blB, warpN * 32 + sl);
            cpa_wait0(); __syncthreads();
        }
    }
    // phase 2: c2 over x (4 chunks)
    for (int c2 = 0; c2 < 4; c2++) {
        const int slot = (c2 + 2) & 3;
        const int sq = 18 + c2;
        if (sq + 1 < 22) stage_A(sq + 1, (sq + 1) & 1);
        if (c2 + 1 < 4) { stage_B2(0, c2 + 1, (c2 + 3) & 3); stage_B2(1, c2 + 1, (c2 + 3) & 3); }
        compute(su + ABASE + (sq & 1) * ABUF, su + slot * SLOT, su + slot * SLOT + BPL, warpN * 32);
        cpa_wait0(); __syncthreads();
    }

    const int g = lane >> 2, q = lane & 3;
#pragma unroll
    for (int mt = 0; mt < 2; mt++)
#pragma unroll
        for (int half2 = 0; half2 < 2; half2++) {
            const int co = co0 + mo + mt * 16 + g + half2 * 8;
            const float bi = b1[co] + b2[co];
            const size_t rowb = ((size_t)(b * COUT + co) * HH + h) * WW;
#pragma unroll
            for (int nt = 0; nt < 4; nt++) {
                const int px = w0p + warpN * 32 + nt * 8 + q * 2;
                float v0 = fmaxf(acc[mt][nt][half2 * 2 + 0] + bi, 0.f);
                float v1 = fmaxf(acc[mt][nt][half2 * 2 + 1] + bi, 0.f);
                *reinterpret_cast<float2*>(out + rowb + px) = make_float2(v0, v1);
            }
        }
}

// ------------------------- scans (exact, f32 NCHW) -------------------------
__global__ void colscan_kernel(float* __restrict__ p)
{
    int idx = blockIdx.x * blockDim.x + threadIdx.x;
    if (idx >= B_ * MID * WW) return;
    int w = idx % WW, bc = idx / WW;
    float* col = p + (size_t)bc * HW + w;
    float m = col[(HH - 1) * WW];
#pragma unroll 4
    for (int h = HH - 2; h >= 0; h--) {
        m = fmaxf(m, col[h * WW]);
        col[h * WW] = m;
    }
}
__global__ void rowscan_add_kernel(const float* __restrict__ p2, float* __restrict__ s)
{
    __shared__ float sm[WW];
    const int t = threadIdx.x;
    const size_t base = (size_t)blockIdx.x * WW;
    sm[t] = p2[base + t];
    __syncthreads();
#pragma unroll
    for (int off = 1; off < WW; off <<= 1) {
        float nv = sm[t];
        if (t + off < WW) nv = fmaxf(nv, sm[t + off]);
        __syncthreads();
        sm[t] = nv;
        __syncthreads();
    }
    s[base + t] += sm[t];
}

// ------------------------- launch -------------------------
extern "C" void kernel_launch(void* const* d_in, const int* in_sizes, int n_in,
                              void* d_out, int out_size)
{
    (void)in_sizes; (void)n_in; (void)out_size;

    const float* x = (const float*)d_in[0];

    float *p1, *p2, *t1, *sc, *bi;
    h16 *xh, *xl, *sh, *sl, *rh, *rl, *wp;
    cudaGetSymbolAddress((void**)&p1, g_p1);
    cudaGetSymbolAddress((void**)&p2, g_p2);
    cudaGetSymbolAddress((void**)&t1, g_t1);
    cudaGetSymbolAddress((void**)&sc, g_scale);
    cudaGetSymbolAddress((void**)&bi, g_bias);
    cudaGetSymbolAddress((void**)&xh, g_xT_hi);
    cudaGetSymbolAddress((void**)&xl, g_xT_lo);
    cudaGetSymbolAddress((void**)&sh, g_sT_hi);
    cudaGetSymbolAddress((void**)&sl, g_sT_lo);
    cudaGetSymbolAddress((void**)&rh, g_rT_hi);
    cudaGetSymbolAddress((void**)&rl, g_rT_lo);
    cudaGetSymbolAddress((void**)&wp, g_w);

    constexpr int SM3 = 4 * (2 * 66 * 128) + 2 * 16384;   // 100352
    cudaFuncSetAttribute(conv3<true>,  cudaFuncAttributeMaxDynamicSharedMemorySize, SM3);
    cudaFuncSetAttribute(conv3<false>, cudaFuncAttributeMaxDynamicSharedMemorySize, SM3);
    cudaFuncSetAttribute(conv_c1c2,    cudaFuncAttributeMaxDynamicSharedMemorySize, SM3);

    // merged BN folding + weight split
    P5 gg = {{(const float*)d_in[2],  (const float*)d_in[7],  (const float*)d_in[12], (const float*)d_in[17], (const float*)d_in[22]}};
    P5 bb = {{(const float*)d_in[3],  (const float*)d_in[8],  (const float*)d_in[13], (const float*)d_in[18], (const float*)d_in[23]}};
    P5 mm = {{(const float*)d_in[4],  (const float*)d_in[9],  (const float*)d_in[14], (const float*)d_in[19], (const float*)d_in[24]}};
    P5 vv = {{(const float*)d_in[5],  (const float*)d_in[10], (const float*)d_in[15], (const float*)d_in[20], (const float*)d_in[25]}};
    P5 ww = {{(const float*)d_in[1],  (const float*)d_in[6],  (const float*)d_in[11], (const float*)d_in[16], (const float*)d_in[21]}};
    bn_prep_all<<<4, 256>>>(gg, bb, mm, vv, sc, bi);
    wsplit_all<<<896, 256>>>(ww, sc, wp);

    // x -> NHWC fp16 hi/lo
    split_T<<<dim3(HW / 32, DIM / 32, B_), 256>>>(x, xh, xl, DIM);

    // p1 + p2 in one launch (grid.y selects branch; grid.x = half-rows)
    conv3<true><<<dim3(B_ * HH * 2, 2), 256, SM3>>>(
        xh, xl, wp + WOFF_P1, wp + WOFF_P2, bi + 0, bi + 128, p1, p2, MID);

    // corner pooling: p1 <- revcummax_H(p1) + revcummax_W(p2)
    colscan_kernel<<<(B_ * MID * WW + 255) / 256, 256>>>(p1);
    rowscan_add_kernel<<<B_ * MID * HH, WW>>>(p2, p1);

    // s -> NHWC fp16 hi/lo
    split_T<<<dim3(HW / 32, MID / 32, B_), 256>>>(p1, sh, sl, MID);

    // fused c1 + c2 -> r (in t1)
    conv_c1c2<<<dim3(B_ * HH * 2, 2), 256, SM3>>>(
        sh, sl, xh, xl, wp + WOFF_C1, wp + WOFF_C2, bi + 256, bi + 512, t1);

    // r -> NHWC fp16 hi/lo; p3
    split_T<<<dim3(HW / 32, DIM / 32, B_), 256>>>(t1, rh, rl, DIM);
    conv3<false><<<dim3(B_ * HH * 2, 2), 256, SM3>>>(
        rh, rl, wp + WOFF_P3, nullptr, bi + 768, nullptr, (float*)d_out, nullptr, DIM);
}